// round 1
// baseline (speedup 1.0000x reference)
#include <cuda_runtime.h>
#include <cuda_bf16.h>
#include <math.h>

// ---------------- problem constants ----------------
#define NN 102400      // nodes
#define EE 819200      // edges
#define DD 120         // input channels
#define HH 200         // hidden
#define CCC 320        // concat dim
#define LL 400         // nodes per graph
#define BB 256         // graphs
#define NSTEPS 8

// ---------------- scratch (device globals; no allocation allowed) ----------
__device__ float g_h0[NN * HH];
__device__ float g_h1[NN * HH];
__device__ float g_s[NN * 2 * HH];
__device__ float g_a[NN * HH];
__device__ float g_gi[NN * 3 * HH];
__device__ float g_gh[NN * 3 * HH];
__device__ int   g_cnt0[NN];
__device__ int   g_cnt1[NN];
__device__ int   g_rowptr[NN + 1];
__device__ int   g_rowfill[NN];
__device__ int   g_col[EE];
__device__ float g_wcat[HH * 2 * HH];

__device__ float g_ht[BB * HH * LL];          // [B,200,400]
__device__ float g_ct[BB * CCC * LL];         // [B,320,400]
__device__ float g_y1pre[BB * HH * 398];
__device__ float g_y1[BB * HH * 198];
__device__ float g_y2pre[BB * HH * 198];
__device__ float g_y2t[BB * 99 * HH];
__device__ float g_z1pre[BB * CCC * 398];
__device__ float g_z1[BB * CCC * 198];
__device__ float g_z2pre[BB * CCC * 198];
__device__ float g_z2t[BB * 99 * CCC];
__device__ float g_yp[BB * 99 * 256];
__device__ float g_zp[BB * 99 * 256];
__device__ float g_avg[BB * 256];
__device__ float g_m1[BB * 128];
__device__ float g_m2[BB * 64];
__device__ float g_hf[BB * 128];
__device__ float g_logits[BB * 2];

// ---------------- small utility kernels ----------------
__global__ void k_init_h(const float* __restrict__ x, float* __restrict__ h) {
    int idx = blockIdx.x * blockDim.x + threadIdx.x;
    if (idx >= NN * HH) return;
    int n = idx / HH, c = idx % HH;
    h[idx] = (c < DD) ? x[(size_t)n * DD + c] : 0.f;
}

__global__ void k_zero_cnt(int* __restrict__ c0, int* __restrict__ c1) {
    int idx = blockIdx.x * blockDim.x + threadIdx.x;
    if (idx < NN) c0[idx] = 0;
    else if (idx < 2 * NN) c1[idx - NN] = 0;
}

__global__ void k_count(const int* __restrict__ eidx, const int* __restrict__ etyp,
                        int* __restrict__ c0, int* __restrict__ c1) {
    int e = blockIdx.x * blockDim.x + threadIdx.x;
    if (e >= EE) return;
    int d = eidx[EE + e];
    if (etyp[e] == 0) atomicAdd(&c0[d], 1);
    else              atomicAdd(&c1[d], 1);
}

__global__ void k_scan(const int* __restrict__ c0, const int* __restrict__ c1,
                       int* __restrict__ rowptr, int* __restrict__ rowfill) {
    __shared__ int ssum[1024];
    const int CH = NN / 1024;   // 100
    int t = threadIdx.x;
    int base = t * CH;
    int s = 0;
    for (int i = 0; i < CH; i++) s += c0[base + i] + c1[base + i];
    ssum[t] = s;
    __syncthreads();
    for (int off = 1; off < 1024; off <<= 1) {
        int v = (t >= off) ? ssum[t - off] : 0;
        __syncthreads();
        ssum[t] += v;
        __syncthreads();
    }
    int run = (t == 0) ? 0 : ssum[t - 1];
    for (int i = 0; i < CH; i++) {
        rowptr[base + i]  = run;
        rowfill[base + i] = run;
        run += c0[base + i] + c1[base + i];
    }
    if (t == 1023) rowptr[NN] = run;
}

__global__ void k_fill(const int* __restrict__ eidx, const int* __restrict__ etyp,
                       int* __restrict__ rowfill, int* __restrict__ col) {
    int e = blockIdx.x * blockDim.x + threadIdx.x;
    if (e >= EE) return;
    int src = eidx[e];
    int d   = eidx[EE + e];
    int et  = etyp[e];
    int p = atomicAdd(&rowfill[d], 1);
    col[p] = src | (et << 31);
}

__global__ void k_wcat(const float* __restrict__ gW, float* __restrict__ wcat) {
    int idx = blockIdx.x * blockDim.x + threadIdx.x;
    if (idx >= HH * 2 * HH) return;
    int o = idx / (2 * HH), k = idx % (2 * HH);
    wcat[idx] = (k < HH) ? gW[(size_t)o * HH + k]
                         : gW[(size_t)HH * HH + (size_t)o * HH + (k - HH)];
}

// warp per node: s[n,0:200] = sum_{type0 in-edges} h[src], s[n,200:400] = type1
__global__ void k_gather(const float* __restrict__ h, const int* __restrict__ rowptr,
                         const int* __restrict__ col, float* __restrict__ s) {
    int warp = (blockIdx.x * blockDim.x + threadIdx.x) >> 5;
    int lane = threadIdx.x & 31;
    if (warp >= NN) return;
    float a0[7], a1[7];
#pragma unroll
    for (int i = 0; i < 7; i++) { a0[i] = 0.f; a1[i] = 0.f; }
    int beg = rowptr[warp], end = rowptr[warp + 1];
    for (int e = beg; e < end; e++) {
        int v = col[e];
        int src = v & 0x7fffffff;
        const float* hr = h + (size_t)src * HH;
        if (v >= 0) {
#pragma unroll
            for (int i = 0; i < 7; i++) {
                int c = lane + i * 32;
                if (c < HH) a0[i] += __ldg(hr + c);
            }
        } else {
#pragma unroll
            for (int i = 0; i < 7; i++) {
                int c = lane + i * 32;
                if (c < HH) a1[i] += __ldg(hr + c);
            }
        }
    }
    float* sr = s + (size_t)warp * (2 * HH);
#pragma unroll
    for (int i = 0; i < 7; i++) {
        int c = lane + i * 32;
        if (c < HH) { sr[c] = a0[i]; sr[HH + c] = a1[i]; }
    }
}

__global__ void k_gru(const float* __restrict__ gi, const float* __restrict__ gh,
                      const float* __restrict__ h, float* __restrict__ hn) {
    int idx = blockIdx.x * blockDim.x + threadIdx.x;
    if (idx >= NN * HH) return;
    int n = idx / HH, c = idx % HH;
    size_t base = (size_t)n * (3 * HH) + c;
    float ir = gi[base], iz = gi[base + HH], inn = gi[base + 2 * HH];
    float hr = gh[base], hz = gh[base + HH], hnn = gh[base + 2 * HH];
    float r = 1.f / (1.f + expf(-(ir + hr)));
    float z = 1.f / (1.f + expf(-(iz + hz)));
    float nv = tanhf(inn + r * hnn);
    hn[idx] = (1.f - z) * nv + z * h[idx];
}

// ---------------- generic tiled GEMM: C[M,Nc] = epi(A[M,K] @ W[Nc,K]^T) ------
// BM=128, BN=64, BK=8, 256 threads, 8x4 per thread. Requires M%128==0, K%8==0.
// EPI 0: + bias[n]; EPI 1: relu(+bias[n]); EPI 2: + c0[m]*b0[n] + c1[m]*b1[n]
template<int EPI>
__global__ __launch_bounds__(256)
void gemm_tn(const float* __restrict__ A, const float* __restrict__ W,
             const float* __restrict__ bias, float* __restrict__ C,
             int M, int Nc, int K,
             const int* __restrict__ cc0, const int* __restrict__ cc1,
             const float* __restrict__ b0, const float* __restrict__ b1) {
    __shared__ float As[8][128];
    __shared__ float Ws[8][64];
    int tid = threadIdx.x;
    int m0 = blockIdx.y * 128;
    int n0 = blockIdx.x * 64;
    int msub = (tid >> 4) * 8;
    int nsub = (tid & 15) * 4;
    float acc[8][4];
#pragma unroll
    for (int i = 0; i < 8; i++)
#pragma unroll
        for (int j = 0; j < 4; j++) acc[i][j] = 0.f;

    int la_m = tid >> 1;
    int la_k = (tid & 1) * 4;
    int lw_n = tid >> 2;
    int lw_k = (tid & 3) * 2;

    for (int k0 = 0; k0 < K; k0 += 8) {
        float4 av = *(const float4*)(A + (size_t)(m0 + la_m) * K + k0 + la_k);
        As[la_k + 0][la_m] = av.x;
        As[la_k + 1][la_m] = av.y;
        As[la_k + 2][la_m] = av.z;
        As[la_k + 3][la_m] = av.w;
        float2 wv = make_float2(0.f, 0.f);
        if (n0 + lw_n < Nc)
            wv = *(const float2*)(W + (size_t)(n0 + lw_n) * K + k0 + lw_k);
        Ws[lw_k + 0][lw_n] = wv.x;
        Ws[lw_k + 1][lw_n] = wv.y;
        __syncthreads();
#pragma unroll
        for (int k = 0; k < 8; k++) {
            float4 a0 = *(const float4*)&As[k][msub];
            float4 a1 = *(const float4*)&As[k][msub + 4];
            float4 bv = *(const float4*)&Ws[k][nsub];
            float am[8] = {a0.x, a0.y, a0.z, a0.w, a1.x, a1.y, a1.z, a1.w};
            float bn[4] = {bv.x, bv.y, bv.z, bv.w};
#pragma unroll
            for (int i = 0; i < 8; i++)
#pragma unroll
                for (int j = 0; j < 4; j++) acc[i][j] += am[i] * bn[j];
        }
        __syncthreads();
    }
#pragma unroll
    for (int i = 0; i < 8; i++) {
        int m = m0 + msub + i;
#pragma unroll
        for (int j = 0; j < 4; j++) {
            int n = n0 + nsub + j;
            if (n < Nc) {
                float v = acc[i][j];
                if (EPI == 0) v += bias[n];
                if (EPI == 1) v = fmaxf(v + bias[n], 0.f);
                if (EPI == 2) v += (float)cc0[m] * b0[n] + (float)cc1[m] * b1[n];
                C[(size_t)m * Nc + n] = v;
            }
        }
    }
}

// ---------------- 1D conv (VALID) + relu: Y[b,o,l] = relu(sum x[b,i,l+k]w[o,i,k]+b)
template<int KW>
__global__ __launch_bounds__(256)
void conv_relu(const float* __restrict__ X, const float* __restrict__ Wt,
               const float* __restrict__ bias, float* __restrict__ Y,
               int CIN, int COUT, int LIN, int LOUT) {
    const int BL = 64, BO = 64, BC = 8;
    const int XW = BL + KW - 1;
    __shared__ float xs[BC][BL + KW - 1];
    __shared__ float ws[BC * KW][BO];
    int b  = blockIdx.z;
    int o0 = blockIdx.y * BO;
    int l0 = blockIdx.x * BL;
    int tid = threadIdx.x;
    int to = (tid & 15) * 4;
    int tl = (tid >> 4) * 4;
    float acc[4][4];
#pragma unroll
    for (int i = 0; i < 4; i++)
#pragma unroll
        for (int j = 0; j < 4; j++) acc[i][j] = 0.f;

    for (int c0 = 0; c0 < CIN; c0 += BC) {
        for (int idx = tid; idx < BC * XW; idx += 256) {
            int kk = idx / XW, ll = idx % XW;
            int l = l0 + ll;
            xs[kk][ll] = (l < LIN) ? X[((size_t)b * CIN + c0 + kk) * LIN + l] : 0.f;
        }
        for (int idx = tid; idx < BC * KW * BO; idx += 256) {
            int r  = idx % (BC * KW);
            int oo = idx / (BC * KW);
            int o = o0 + oo;
            int kk = r / KW, kw = r % KW;
            ws[r][oo] = (o < COUT) ? Wt[((size_t)o * CIN + c0 + kk) * KW + kw] : 0.f;
        }
        __syncthreads();
#pragma unroll
        for (int kk = 0; kk < BC; kk++) {
            float xv[4 + KW - 1];
#pragma unroll
            for (int t = 0; t < 4 + KW - 1; t++) xv[t] = xs[kk][tl + t];
#pragma unroll
            for (int kw = 0; kw < KW; kw++) {
                float4 wv = *(const float4*)&ws[kk * KW + kw][to];
                float wn[4] = {wv.x, wv.y, wv.z, wv.w};
#pragma unroll
                for (int oo = 0; oo < 4; oo++)
#pragma unroll
                    for (int ll = 0; ll < 4; ll++)
                        acc[oo][ll] += wn[oo] * xv[ll + kw];
            }
        }
        __syncthreads();
    }
#pragma unroll
    for (int oo = 0; oo < 4; oo++) {
        int o = o0 + to + oo;
#pragma unroll
        for (int ll = 0; ll < 4; ll++) {
            int l = l0 + tl + ll;
            if (o < COUT && l < LOUT)
                Y[((size_t)b * COUT + o) * LOUT + l] = fmaxf(acc[oo][ll] + bias[o], 0.f);
        }
    }
}

__global__ void k_pool3(const float* __restrict__ in, float* __restrict__ out,
                        int C, int LIN, int LOUT) {
    int idx = blockIdx.x * blockDim.x + threadIdx.x;
    int total = BB * C * LOUT;
    if (idx >= total) return;
    int l = idx % LOUT;
    int bc = idx / LOUT;
    const float* p = in + (size_t)bc * LIN + 2 * l;
    out[idx] = fmaxf(fmaxf(p[0], p[1]), p[2]);
}

// pool k=2 s=2, writing transposed: out[(b*LOUT+l)*C + c]
__global__ void k_pool2t(const float* __restrict__ in, float* __restrict__ out,
                         int C, int LIN, int LOUT) {
    int idx = blockIdx.x * blockDim.x + threadIdx.x;
    int total = BB * LOUT * C;
    if (idx >= total) return;
    int c = idx % C;
    int l = (idx / C) % LOUT;
    int b = idx / (C * LOUT);
    const float* p = in + ((size_t)b * C + c) * LIN + 2 * l;
    out[idx] = fmaxf(p[0], p[1]);
}

// transpose src[(b*400+l)*Cs + c] -> dst[(b*Ctot + co + c)*400 + l]
__global__ void k_transpose(const float* __restrict__ src, float* __restrict__ dst,
                            int Cs, int co, int Ctot) {
    __shared__ float t[32][33];
    int b = blockIdx.z;
    int l0 = blockIdx.x * 32, c0 = blockIdx.y * 32;
    int tx = threadIdx.x, ty = threadIdx.y;
#pragma unroll
    for (int i = 0; i < 4; i++) {
        int l = l0 + ty + i * 8, c = c0 + tx;
        if (l < LL && c < Cs)
            t[tx][ty + i * 8] = src[((size_t)b * LL + l) * Cs + c];
    }
    __syncthreads();
#pragma unroll
    for (int i = 0; i < 4; i++) {
        int c = c0 + ty + i * 8, l = l0 + tx;
        if (c < Cs && l < LL)
            dst[((size_t)b * Ctot + co + c) * LL + l] = t[ty + i * 8][tx];
    }
}

__global__ void k_avg(const float* __restrict__ yp, const float* __restrict__ zp,
                      float* __restrict__ avg) {
    int idx = blockIdx.x * blockDim.x + threadIdx.x;
    if (idx >= BB * 256) return;
    int j = idx & 255;
    int b = idx >> 8;
    float s = 0.f;
    for (int l = 0; l < 99; l++) {
        size_t off = ((size_t)b * 99 + l) * 256 + j;
        s += yp[off] * zp[off];
    }
    avg[idx] = s * (1.f / 99.f);
}

__global__ void k_pack(const float* __restrict__ logits, const float* __restrict__ hf,
                       float* __restrict__ out, int out_size) {
    int i = blockIdx.x * blockDim.x + threadIdx.x;
    if (i >= out_size) return;
    out[i] = (i < BB * 2) ? logits[i] : hf[i - BB * 2];
}

// ---------------- launcher ----------------
static float* symf(const void* p) { return (float*)p; }

extern "C" void kernel_launch(void* const* d_in, const int* in_sizes, int n_in,
                              void* d_out, int out_size) {
    const float* x       = (const float*)d_in[0];
    const int*   eidx    = (const int*)d_in[1];
    const int*   etyp    = (const int*)d_in[2];
    const float* ggnnW   = (const float*)d_in[3];
    const float* ggnnB   = (const float*)d_in[4];
    const float* Wih     = (const float*)d_in[5];
    const float* Whh     = (const float*)d_in[6];
    const float* bih     = (const float*)d_in[7];
    const float* bhh     = (const float*)d_in[8];
    const float* c1w     = (const float*)d_in[9];
    const float* c1b     = (const float*)d_in[10];
    const float* c2w     = (const float*)d_in[11];
    const float* c2b     = (const float*)d_in[12];
    const float* cc1w    = (const float*)d_in[13];
    const float* cc1b    = (const float*)d_in[14];
    const float* cc2w    = (const float*)d_in[15];
    const float* cc2b    = (const float*)d_in[16];
    const float* yw      = (const float*)d_in[17];
    const float* yb      = (const float*)d_in[18];
    const float* zw      = (const float*)d_in[19];
    const float* zb      = (const float*)d_in[20];
    const float* l1w     = (const float*)d_in[21];
    const float* l1b     = (const float*)d_in[22];
    const float* f1w     = (const float*)d_in[23];
    const float* f1b     = (const float*)d_in[24];
    const float* f2w     = (const float*)d_in[25];
    const float* f2b     = (const float*)d_in[26];
    const float* clsw    = (const float*)d_in[27];
    const float* clsb    = (const float*)d_in[28];
    float* out = (float*)d_out;

    void* p;
#define GET(name, sym) cudaGetSymbolAddress(&p, sym); float* name = (float*)p;
#define GETI(name, sym) cudaGetSymbolAddress(&p, sym); int* name = (int*)p;
    GET(h0, g_h0) GET(h1, g_h1) GET(sb, g_s) GET(ab, g_a) GET(gi, g_gi) GET(gh, g_gh)
    GETI(cnt0, g_cnt0) GETI(cnt1, g_cnt1) GETI(rowptr, g_rowptr) GETI(rowfill, g_rowfill)
    GETI(colv, g_col)
    GET(wcat, g_wcat)
    GET(ht, g_ht) GET(ct, g_ct)
    GET(y1pre, g_y1pre) GET(y1, g_y1) GET(y2pre, g_y2pre) GET(y2t, g_y2t)
    GET(z1pre, g_z1pre) GET(z1, g_z1) GET(z2pre, g_z2pre) GET(z2t, g_z2t)
    GET(yp, g_yp) GET(zp, g_zp) GET(avg, g_avg)
    GET(m1, g_m1) GET(m2, g_m2) GET(hf, g_hf) GET(logits, g_logits)
#undef GET
#undef GETI

    // --- graph preprocessing (replayed every call; deterministic work) ---
    k_init_h<<<(NN * HH + 255) / 256, 256>>>(x, h0);
    k_zero_cnt<<<(2 * NN + 255) / 256, 256>>>(cnt0, cnt1);
    k_count<<<EE / 256, 256>>>(eidx, etyp, cnt0, cnt1);
    k_scan<<<1, 1024>>>(cnt0, cnt1, rowptr, rowfill);
    k_fill<<<EE / 256, 256>>>(eidx, etyp, rowfill, colv);
    k_wcat<<<(HH * 2 * HH + 255) / 256, 256>>>(ggnnW, wcat);

    // --- 8 GGNN steps ---
    for (int s = 0; s < NSTEPS; s++) {
        float* hin  = (s & 1) ? h1 : h0;
        float* hout = (s & 1) ? h0 : h1;
        k_gather<<<NN / 8, 256>>>(hin, rowptr, colv, sb);
        gemm_tn<2><<<dim3(4, NN / 128), 256>>>(sb, wcat, nullptr, ab,
                                               NN, HH, 2 * HH, cnt0, cnt1, ggnnB, ggnnB + HH);
        gemm_tn<0><<<dim3(10, NN / 128), 256>>>(ab, Wih, bih, gi, NN, 3 * HH, HH,
                                                nullptr, nullptr, nullptr, nullptr);
        gemm_tn<0><<<dim3(10, NN / 128), 256>>>(hin, Whh, bhh, gh, NN, 3 * HH, HH,
                                                nullptr, nullptr, nullptr, nullptr);
        k_gru<<<(NN * HH + 255) / 256, 256>>>(gi, gh, hin, hout);
    }
    float* hfin = h0;   // after 8 steps result lives in h0

    // --- readout ---
    dim3 tb(32, 8);
    k_transpose<<<dim3(13, 7, BB), tb>>>(hfin, ht, HH, 0, HH);
    k_transpose<<<dim3(13, 4, BB), tb>>>(x, ct, DD, 0, CCC);
    k_transpose<<<dim3(13, 7, BB), tb>>>(hfin, ct, HH, DD, CCC);

    conv_relu<3><<<dim3(7, 4, BB), 256>>>(ht, c1w, c1b, y1pre, HH, HH, 400, 398);
    k_pool3<<<(BB * HH * 198 + 255) / 256, 256>>>(y1pre, y1, HH, 398, 198);
    conv_relu<1><<<dim3(4, 4, BB), 256>>>(y1, c2w, c2b, y2pre, HH, HH, 198, 198);
    k_pool2t<<<(BB * 99 * HH + 255) / 256, 256>>>(y2pre, y2t, HH, 198, 99);

    conv_relu<3><<<dim3(7, 5, BB), 256>>>(ct, cc1w, cc1b, z1pre, CCC, CCC, 400, 398);
    k_pool3<<<(BB * CCC * 198 + 255) / 256, 256>>>(z1pre, z1, CCC, 398, 198);
    conv_relu<1><<<dim3(4, 5, BB), 256>>>(z1, cc2w, cc2b, z2pre, CCC, CCC, 198, 198);
    k_pool2t<<<(BB * 99 * CCC + 255) / 256, 256>>>(z2pre, z2t, CCC, 198, 99);

    gemm_tn<0><<<dim3(4, (BB * 99) / 128), 256>>>(y2t, yw, yb, yp, BB * 99, 256, HH,
                                                  nullptr, nullptr, nullptr, nullptr);
    gemm_tn<0><<<dim3(4, (BB * 99) / 128), 256>>>(z2t, zw, zb, zp, BB * 99, 256, CCC,
                                                  nullptr, nullptr, nullptr, nullptr);
    k_avg<<<(BB * 256 + 255) / 256, 256>>>(yp, zp, avg);

    gemm_tn<1><<<dim3(2, 2), 256>>>(avg, l1w, l1b, m1, BB, 128, 256,
                                    nullptr, nullptr, nullptr, nullptr);
    gemm_tn<1><<<dim3(1, 2), 256>>>(m1, f1w, f1b, m2, BB, 64, 128,
                                    nullptr, nullptr, nullptr, nullptr);
    gemm_tn<1><<<dim3(2, 2), 256>>>(m2, f2w, f2b, hf, BB, 128, 64,
                                    nullptr, nullptr, nullptr, nullptr);
    gemm_tn<0><<<dim3(1, 2), 256>>>(hf, clsw, clsb, logits, BB, 2, 128,
                                    nullptr, nullptr, nullptr, nullptr);

    k_pack<<<(out_size + 255) / 256, 256>>>(logits, hf, out, out_size);
    (void)n_in; (void)in_sizes; (void)symf;
}

// round 3
// speedup vs baseline: 1.4097x; 1.4097x over previous
#include <cuda_runtime.h>
#include <cuda_bf16.h>
#include <math.h>
#include <stdint.h>

// ---------------- problem constants ----------------
#define NN 102400
#define EE 819200
#define DD 120
#define HH 200
#define CCC 320
#define LL 400
#define BB 256
#define NSTEPS 8
#define M2 25344          // BB*99 rows for mlp GEMMs

// ---------------- PTX helpers (sm_80-era, safe on base sm_103 target) ------
__device__ __forceinline__ uint32_t smem_u32(const void* p) {
    uint32_t a;
    asm("{ .reg .u64 t; cvta.to.shared.u64 t, %1; cvt.u32.u64 %0, t; }" : "=r"(a) : "l"(p));
    return a;
}

#define CP_ASYNC16(dst, src) \
    asm volatile("cp.async.cg.shared.global [%0], [%1], 16;" :: "r"(dst), "l"(src) : "memory")
#define CP_ASYNC16Z(dst, src, sz) \
    asm volatile("cp.async.cg.shared.global [%0], [%1], 16, %2;" :: "r"(dst), "l"(src), "r"(sz) : "memory")
#define CP_COMMIT() asm volatile("cp.async.commit_group;" ::: "memory")
#define CP_WAIT(n)  asm volatile("cp.async.wait_group %0;" :: "n"(n) : "memory")

#define LDSM4(r, addr) \
    asm volatile("ldmatrix.sync.aligned.m8n8.x4.shared.b16 {%0,%1,%2,%3}, [%4];" \
        : "=r"((r)[0]), "=r"((r)[1]), "=r"((r)[2]), "=r"((r)[3]) : "r"(addr))

#define MMA16816(d, a, bx, by) \
    asm volatile("mma.sync.aligned.m16n8k16.row.col.f32.bf16.bf16.f32 " \
        "{%0,%1,%2,%3}, {%4,%5,%6,%7}, {%8,%9}, {%0,%1,%2,%3};" \
        : "+f"((d)[0]), "+f"((d)[1]), "+f"((d)[2]), "+f"((d)[3]) \
        : "r"((a)[0]), "r"((a)[1]), "r"((a)[2]), "r"((a)[3]), "r"(bx), "r"(by))

__device__ __forceinline__ void split2(float v, __nv_bfloat16& hi, __nv_bfloat16& lo) {
    hi = __float2bfloat16(v);
    lo = __float2bfloat16(v - __bfloat162float(hi));
}
__device__ __forceinline__ uint32_t packbf(__nv_bfloat16 a, __nv_bfloat16 b) {
    return (uint32_t)__bfloat16_as_ushort(a) | ((uint32_t)__bfloat16_as_ushort(b) << 16);
}

// ---------------- scratch (device globals) ----------------
__device__ __align__(256) float g_h0[NN * HH];
__device__ __align__(256) float g_h1[NN * HH];
__device__ __align__(256) __nv_bfloat16 g_h0s[NN * 512];
__device__ __align__(256) __nv_bfloat16 g_h1s[NN * 512];
__device__ __align__(256) __nv_bfloat16 g_ss[NN * 896];
__device__ __align__(256) __nv_bfloat16 g_as[NN * 512];
__device__ __align__(256) float g_gi[NN * 600];
__device__ __align__(256) float g_gh[NN * 600];
__device__ int   g_cnt0[NN];
__device__ int   g_cnt1[NN];
__device__ int   g_rowptr[NN + 1];
__device__ int   g_rowfill[NN];
__device__ int   g_col[EE];

__device__ __align__(256) __nv_bfloat16 g_wcat_s[200 * 896];
__device__ __align__(256) __nv_bfloat16 g_wih_s[600 * 512];
__device__ __align__(256) __nv_bfloat16 g_whh_s[600 * 512];
__device__ __align__(256) __nv_bfloat16 g_myw_s[256 * 512];
__device__ __align__(256) __nv_bfloat16 g_mzw_s[256 * 640];

__device__ __align__(256) float g_ht[BB * HH * LL];
__device__ __align__(256) float g_ct[BB * CCC * LL];
__device__ __align__(256) float g_y1pre[BB * HH * 398];
__device__ __align__(256) float g_y1[BB * HH * 198];
__device__ __align__(256) float g_y2pre[BB * HH * 198];
__device__ __align__(256) __nv_bfloat16 g_y2ts[M2 * 512];
__device__ __align__(256) float g_z1pre[BB * CCC * 398];
__device__ __align__(256) float g_z1[BB * CCC * 198];
__device__ __align__(256) float g_z2pre[BB * CCC * 198];
__device__ __align__(256) __nv_bfloat16 g_z2ts[M2 * 640];
__device__ __align__(256) float g_yp[M2 * 256];
__device__ __align__(256) float g_zp[M2 * 256];
__device__ float g_avg[BB * 256];
__device__ float g_m1[BB * 128];
__device__ float g_m2[BB * 64];
__device__ float g_hf[BB * 128];
__device__ float g_logits[BB * 2];

// ---------------- HMMA split-bf16 GEMM ----------------
// C[M, Ncols] = sum over 3 segments: (Ah,Bh),(Al,Bh),(Ah,Bl)
// A: [M, 2*KPAD] bf16 (hi|lo). B: [Nrows=Ncols, 2*KPAD] bf16 (pad cols zeroed).
// Tile 128x64, BK=64, 256 threads, cp.async double buffer, ldmatrix fragments.
// EPI 0: C[m*ldc+n] = v + bias[n] (fp32)
// EPI 1: v += cc0[m]*bias[n] + cc1[m]*b1[n]; split-bf16 to OS [M, 2*okpad]
//        (n >= Ncols within the 64-tile writes zeros -> pads stay clean)
#define ROWB 144   // smem row stride bytes (64 halves + 8 pad)
template<int KPAD, int EPI>
__global__ void __launch_bounds__(256, 2)
gemm_mma(const __nv_bfloat16* __restrict__ A, int lda,
         const __nv_bfloat16* __restrict__ Bw, int ldb, int Ncols,
         float* __restrict__ C, int ldc, const float* __restrict__ bias,
         __nv_bfloat16* __restrict__ OS, int okpad,
         const int* __restrict__ cc0, const int* __restrict__ cc1,
         const float* __restrict__ b1) {
    constexpr int CPS = KPAD / 64;
    constexpr int NCH = 3 * CPS;
    constexpr int ASTG = 128 * ROWB;           // 18432
    constexpr int BBASE = 2 * ASTG;            // 36864
    constexpr int BSTG = 64 * ROWB;            // 9216
    extern __shared__ char smem[];
    const uint32_t sb = smem_u32(smem);
    const int tid = threadIdx.x, lane = tid & 31, wid = tid >> 5;
    const int m0 = blockIdx.y * 128, n0 = blockIdx.x * 64;
    const int wm = wid >> 1, wn = wid & 1;

    float acc[2][4][4];
#pragma unroll
    for (int i = 0; i < 2; i++)
#pragma unroll
        for (int j = 0; j < 4; j++)
#pragma unroll
            for (int k = 0; k < 4; k++) acc[i][j][k] = 0.f;

    auto load_stage = [&](int i, int st) {
        int seg = i / CPS, c = i - seg * CPS;
        int aoff = (seg == 1 ? KPAD : 0) + c * 64;
        int boff = (seg == 2 ? KPAD : 0) + c * 64;
        uint32_t sA = sb + st * ASTG;
        uint32_t sB = sb + BBASE + st * BSTG;
#pragma unroll
        for (int t = 0; t < 4; t++) {
            int idx = tid + t * 256;
            int row = idx >> 3, j = idx & 7;
            const __nv_bfloat16* src = A + (size_t)(m0 + row) * lda + aoff + j * 8;
            CP_ASYNC16(sA + row * ROWB + j * 16, src);
        }
#pragma unroll
        for (int t = 0; t < 2; t++) {
            int idx = tid + t * 256;
            int row = idx >> 3, j = idx & 7;
            int n = n0 + row;
            int ok = (n < Ncols);
            const __nv_bfloat16* src = Bw + (size_t)(ok ? n : 0) * ldb + boff + j * 8;
            CP_ASYNC16Z(sB + row * ROWB + j * 16, src, ok ? 16 : 0);
        }
        CP_COMMIT();
    };

    // per-lane ldmatrix source addresses (within a stage)
    const uint32_t aLane = (uint32_t)((wm * 32 + (lane & 15)) * ROWB + ((lane >> 4) * 8) * 2);
    const uint32_t bLane = (uint32_t)((wn * 32 + (lane & 7) + ((lane >> 4) * 8)) * ROWB +
                                      (((lane >> 3) & 1) * 8) * 2);

    load_stage(0, 0);
    for (int i = 0; i < NCH; i++) {
        int st = i & 1;
        if (i + 1 < NCH) { load_stage(i + 1, (i + 1) & 1); CP_WAIT(1); }
        else             { CP_WAIT(0); }
        __syncthreads();
        uint32_t aB = sb + st * ASTG + aLane;
        uint32_t bB = sb + BBASE + st * BSTG + bLane;
#pragma unroll
        for (int ks = 0; ks < 4; ks++) {
            uint32_t a0[4], a1[4], b0[4], b1v[4];
            LDSM4(a0, aB + ks * 32);
            LDSM4(a1, aB + 16 * ROWB + ks * 32);
            LDSM4(b0, bB + ks * 32);
            LDSM4(b1v, bB + 16 * ROWB + ks * 32);
            MMA16816(acc[0][0], a0, b0[0], b0[1]);
            MMA16816(acc[0][1], a0, b0[2], b0[3]);
            MMA16816(acc[0][2], a0, b1v[0], b1v[1]);
            MMA16816(acc[0][3], a0, b1v[2], b1v[3]);
            MMA16816(acc[1][0], a1, b0[0], b0[1]);
            MMA16816(acc[1][1], a1, b0[2], b0[3]);
            MMA16816(acc[1][2], a1, b1v[0], b1v[1]);
            MMA16816(acc[1][3], a1, b1v[2], b1v[3]);
        }
        __syncthreads();
    }

    // epilogue
    const int g = lane >> 2, tg = lane & 3;
#pragma unroll
    for (int mi = 0; mi < 2; mi++) {
        int mA = m0 + wm * 32 + mi * 16 + g;     // rows mA, mA+8
#pragma unroll
        for (int nj = 0; nj < 4; nj++) {
            int n = n0 + wn * 32 + nj * 8 + tg * 2;
            float v0 = acc[mi][nj][0], v1 = acc[mi][nj][1];
            float v2 = acc[mi][nj][2], v3 = acc[mi][nj][3];
            if (EPI == 0) {
                if (n < Ncols) {
                    float bn = bias[n], bn1 = bias[n + 1];
                    *(float2*)&C[(size_t)mA * ldc + n] = make_float2(v0 + bn, v1 + bn1);
                    *(float2*)&C[(size_t)(mA + 8) * ldc + n] = make_float2(v2 + bn, v3 + bn1);
                }
            } else {
                uint32_t hi0 = 0, lo0 = 0, hi1 = 0, lo1 = 0;
                if (n < Ncols) {
                    float bn = bias[n], bn1 = bias[n + 1];
                    float dn = b1[n], dn1 = b1[n + 1];
                    float q0a = (float)cc0[mA], q1a = (float)cc1[mA];
                    float q0b = (float)cc0[mA + 8], q1b = (float)cc1[mA + 8];
                    v0 += q0a * bn + q1a * dn;   v1 += q0a * bn1 + q1a * dn1;
                    v2 += q0b * bn + q1b * dn;   v3 += q0b * bn1 + q1b * dn1;
                    __nv_bfloat16 h0, l0, h1, l1;
                    split2(v0, h0, l0); split2(v1, h1, l1);
                    hi0 = packbf(h0, h1); lo0 = packbf(l0, l1);
                    split2(v2, h0, l0); split2(v3, h1, l1);
                    hi1 = packbf(h0, h1); lo1 = packbf(l0, l1);
                }
                if (n < okpad) {
                    *(uint32_t*)&OS[(size_t)mA * (2 * okpad) + n] = hi0;
                    *(uint32_t*)&OS[(size_t)mA * (2 * okpad) + okpad + n] = lo0;
                    *(uint32_t*)&OS[(size_t)(mA + 8) * (2 * okpad) + n] = hi1;
                    *(uint32_t*)&OS[(size_t)(mA + 8) * (2 * okpad) + okpad + n] = lo1;
                }
            }
        }
    }
}

// ---------------- small utility kernels ----------------
// writes full 256-wide padded rows (pads = 0)
__global__ void k_init_h(const float* __restrict__ x, float* __restrict__ h,
                         __nv_bfloat16* __restrict__ hs) {
    int idx = blockIdx.x * blockDim.x + threadIdx.x;
    if (idx >= NN * 256) return;
    int n = idx >> 8, c = idx & 255;
    float v = 0.f;
    if (c < DD) v = x[(size_t)n * DD + c];
    if (c < HH) h[(size_t)n * HH + c] = v;
    __nv_bfloat16 hi, lo;
    split2(v, hi, lo);
    hs[(size_t)n * 512 + c] = hi;
    hs[(size_t)n * 512 + 256 + c] = lo;
}

__global__ void k_zero_cnt(int* __restrict__ c0, int* __restrict__ c1) {
    int idx = blockIdx.x * blockDim.x + threadIdx.x;
    if (idx < NN) c0[idx] = 0;
    else if (idx < 2 * NN) c1[idx - NN] = 0;
}

__global__ void k_count(const int* __restrict__ eidx, const int* __restrict__ etyp,
                        int* __restrict__ c0, int* __restrict__ c1) {
    int e = blockIdx.x * blockDim.x + threadIdx.x;
    if (e >= EE) return;
    int d = eidx[EE + e];
    if (etyp[e] == 0) atomicAdd(&c0[d], 1);
    else              atomicAdd(&c1[d], 1);
}

__global__ void k_scan(const int* __restrict__ c0, const int* __restrict__ c1,
                       int* __restrict__ rowptr, int* __restrict__ rowfill) {
    __shared__ int ssum[1024];
    const int CH = NN / 1024;
    int t = threadIdx.x;
    int base = t * CH;
    int s = 0;
    for (int i = 0; i < CH; i++) s += c0[base + i] + c1[base + i];
    ssum[t] = s;
    __syncthreads();
    for (int off = 1; off < 1024; off <<= 1) {
        int v = (t >= off) ? ssum[t - off] : 0;
        __syncthreads();
        ssum[t] += v;
        __syncthreads();
    }
    int run = (t == 0) ? 0 : ssum[t - 1];
    for (int i = 0; i < CH; i++) {
        rowptr[base + i]  = run;
        rowfill[base + i] = run;
        run += c0[base + i] + c1[base + i];
    }
    if (t == 1023) rowptr[NN] = run;
}

__global__ void k_fill(const int* __restrict__ eidx, const int* __restrict__ etyp,
                       int* __restrict__ rowfill, int* __restrict__ col) {
    int e = blockIdx.x * blockDim.x + threadIdx.x;
    if (e >= EE) return;
    int src = eidx[e];
    int d   = eidx[EE + e];
    int et  = etyp[e];
    int p = atomicAdd(&rowfill[d], 1);
    col[p] = src | (et << 31);
}

// weight pack with zero pads: W[Nr, K] fp32 -> [Nr, 2*KPAD] bf16 (hi | lo)
__global__ void k_split_w(const float* __restrict__ src, __nv_bfloat16* __restrict__ dst,
                          int Nr, int K, int KPAD) {
    int idx = blockIdx.x * blockDim.x + threadIdx.x;
    if (idx >= Nr * KPAD) return;
    int n = idx / KPAD, k = idx % KPAD;
    float v = (k < K) ? src[(size_t)n * K + k] : 0.f;
    __nv_bfloat16 hi, lo;
    split2(v, hi, lo);
    dst[(size_t)n * 2 * KPAD + k] = hi;
    dst[(size_t)n * 2 * KPAD + KPAD + k] = lo;
}

// wcat pack with zero pads: [200 rows, 2*448]
__global__ void k_wcat_split(const float* __restrict__ gW, __nv_bfloat16* __restrict__ dst) {
    int idx = blockIdx.x * blockDim.x + threadIdx.x;
    if (idx >= 200 * 448) return;
    int o = idx / 448, k = idx % 448;
    float v = 0.f;
    if (k < 200)      v = gW[(size_t)o * 200 + k];
    else if (k < 400) v = gW[(size_t)200 * 200 + (size_t)o * 200 + (k - 200)];
    __nv_bfloat16 hi, lo;
    split2(v, hi, lo);
    dst[(size_t)o * 896 + k] = hi;
    dst[(size_t)o * 896 + 448 + k] = lo;
}

// warp per node: split-bf16 output [node, 896], pads zeroed
__global__ void k_gather(const float* __restrict__ h, const int* __restrict__ rowptr,
                         const int* __restrict__ col, __nv_bfloat16* __restrict__ s) {
    int warp = (blockIdx.x * blockDim.x + threadIdx.x) >> 5;
    int lane = threadIdx.x & 31;
    if (warp >= NN) return;
    float a0[7], a1[7];
#pragma unroll
    for (int i = 0; i < 7; i++) { a0[i] = 0.f; a1[i] = 0.f; }
    int beg = rowptr[warp], end = rowptr[warp + 1];
    for (int e = beg; e < end; e++) {
        int v = col[e];
        int src = v & 0x7fffffff;
        const float* hr = h + (size_t)src * HH;
        if (v >= 0) {
#pragma unroll
            for (int i = 0; i < 7; i++) {
                int c = lane + i * 32;
                if (c < HH) a0[i] += __ldg(hr + c);
            }
        } else {
#pragma unroll
            for (int i = 0; i < 7; i++) {
                int c = lane + i * 32;
                if (c < HH) a1[i] += __ldg(hr + c);
            }
        }
    }
    __nv_bfloat16* sr = s + (size_t)warp * 896;
#pragma unroll
    for (int i = 0; i < 7; i++) {
        int c = lane + i * 32;
        if (c < HH) {
            __nv_bfloat16 hi, lo;
            split2(a0[i], hi, lo);
            sr[c] = hi; sr[448 + c] = lo;
            split2(a1[i], hi, lo);
            sr[200 + c] = hi; sr[648 + c] = lo;
        }
    }
    __nv_bfloat16 z = __float2bfloat16(0.f);
    for (int c = 400 + lane; c < 448; c += 32) { sr[c] = z; sr[448 + c] = z; }
}

// full 256-wide padded rows (pads = 0)
__global__ void k_gru(const float* __restrict__ gi, const float* __restrict__ gh,
                      const float* __restrict__ h, float* __restrict__ hn,
                      __nv_bfloat16* __restrict__ hns) {
    int idx = blockIdx.x * blockDim.x + threadIdx.x;
    if (idx >= NN * 256) return;
    int n = idx >> 8, c = idx & 255;
    __nv_bfloat16* hp = hns + (size_t)n * 512;
    if (c >= HH) {
        __nv_bfloat16 z = __float2bfloat16(0.f);
        hp[c] = z; hp[256 + c] = z;
        return;
    }
    size_t base = (size_t)n * (3 * HH) + c;
    float ir = gi[base], iz = gi[base + HH], inn = gi[base + 2 * HH];
    float hr = gh[base], hz = gh[base + HH], hnn = gh[base + 2 * HH];
    float r = 1.f / (1.f + expf(-(ir + hr)));
    float z = 1.f / (1.f + expf(-(iz + hz)));
    float nv = tanhf(inn + r * hnn);
    float v = (1.f - z) * nv + z * h[(size_t)n * HH + c];
    hn[(size_t)n * HH + c] = v;
    __nv_bfloat16 hi, lo;
    split2(v, hi, lo);
    hp[c] = hi;
    hp[256 + c] = lo;
}

// ---------------- SIMT GEMM (tiny head only) ----------------
template<int EPI>
__global__ __launch_bounds__(256)
void gemm_tn(const float* __restrict__ A, const float* __restrict__ W,
             const float* __restrict__ bias, float* __restrict__ C,
             int M, int Nc, int K) {
    __shared__ float As[8][128];
    __shared__ float Ws[8][64];
    int tid = threadIdx.x;
    int m0 = blockIdx.y * 128;
    int n0 = blockIdx.x * 64;
    int msub = (tid >> 4) * 8;
    int nsub = (tid & 15) * 4;
    float acc[8][4];
#pragma unroll
    for (int i = 0; i < 8; i++)
#pragma unroll
        for (int j = 0; j < 4; j++) acc[i][j] = 0.f;

    int la_m = tid >> 1;
    int la_k = (tid & 1) * 4;
    int lw_n = tid >> 2;
    int lw_k = (tid & 3) * 2;

    for (int k0 = 0; k0 < K; k0 += 8) {
        float4 av = *(const float4*)(A + (size_t)(m0 + la_m) * K + k0 + la_k);
        As[la_k + 0][la_m] = av.x;
        As[la_k + 1][la_m] = av.y;
        As[la_k + 2][la_m] = av.z;
        As[la_k + 3][la_m] = av.w;
        float2 wv = make_float2(0.f, 0.f);
        if (n0 + lw_n < Nc)
            wv = *(const float2*)(W + (size_t)(n0 + lw_n) * K + k0 + lw_k);
        Ws[lw_k + 0][lw_n] = wv.x;
        Ws[lw_k + 1][lw_n] = wv.y;
        __syncthreads();
#pragma unroll
        for (int k = 0; k < 8; k++) {
            float4 a0 = *(const float4*)&As[k][msub];
            float4 a1 = *(const float4*)&As[k][msub + 4];
            float4 bv = *(const float4*)&Ws[k][nsub];
            float am[8] = {a0.x, a0.y, a0.z, a0.w, a1.x, a1.y, a1.z, a1.w};
            float bn[4] = {bv.x, bv.y, bv.z, bv.w};
#pragma unroll
            for (int i = 0; i < 8; i++)
#pragma unroll
                for (int j = 0; j < 4; j++) acc[i][j] += am[i] * bn[j];
        }
        __syncthreads();
    }
#pragma unroll
    for (int i = 0; i < 8; i++) {
        int m = m0 + msub + i;
#pragma unroll
        for (int j = 0; j < 4; j++) {
            int n = n0 + nsub + j;
            if (n < Nc) {
                float v = acc[i][j] + bias[n];
                if (EPI == 1) v = fmaxf(v, 0.f);
                C[(size_t)m * Nc + n] = v;
            }
        }
    }
}

// ---------------- conv + pool ----------------
template<int KW>
__global__ __launch_bounds__(256)
void conv_relu(const float* __restrict__ X, const float* __restrict__ Wt,
               const float* __restrict__ bias, float* __restrict__ Y,
               int CIN, int COUT, int LIN, int LOUT) {
    const int BL = 64, BO = 64, BC = 8;
    const int XW = BL + KW - 1;
    __shared__ float xs[BC][BL + KW - 1];
    __shared__ float ws[BC * KW][BO];
    int b  = blockIdx.z;
    int o0 = blockIdx.y * BO;
    int l0 = blockIdx.x * BL;
    int tid = threadIdx.x;
    int to = (tid & 15) * 4;
    int tl = (tid >> 4) * 4;
    float acc[4][4];
#pragma unroll
    for (int i = 0; i < 4; i++)
#pragma unroll
        for (int j = 0; j < 4; j++) acc[i][j] = 0.f;

    for (int c0 = 0; c0 < CIN; c0 += BC) {
        for (int idx = tid; idx < BC * XW; idx += 256) {
            int kk = idx / XW, ll = idx % XW;
            int l = l0 + ll;
            xs[kk][ll] = (l < LIN) ? X[((size_t)b * CIN + c0 + kk) * LIN + l] : 0.f;
        }
        for (int idx = tid; idx < BC * KW * BO; idx += 256) {
            int r  = idx % (BC * KW);
            int oo = idx / (BC * KW);
            int o = o0 + oo;
            int kk = r / KW, kw = r % KW;
            ws[r][oo] = (o < COUT) ? Wt[((size_t)o * CIN + c0 + kk) * KW + kw] : 0.f;
        }
        __syncthreads();
#pragma unroll
        for (int kk = 0; kk < BC; kk++) {
            float xv[4 + KW - 1];
#pragma unroll
            for (int t = 0; t < 4 + KW - 1; t++) xv[t] = xs[kk][tl + t];
#pragma unroll
            for (int kw = 0; kw < KW; kw++) {
                float4 wv = *(const float4*)&ws[kk * KW + kw][to];
                float wn[4] = {wv.x, wv.y, wv.z, wv.w};
#pragma unroll
                for (int oo = 0; oo < 4; oo++)
#pragma unroll
                    for (int ll = 0; ll < 4; ll++)
                        acc[oo][ll] += wn[oo] * xv[ll + kw];
            }
        }
        __syncthreads();
    }
#pragma unroll
    for (int oo = 0; oo < 4; oo++) {
        int o = o0 + to + oo;
#pragma unroll
        for (int ll = 0; ll < 4; ll++) {
            int l = l0 + tl + ll;
            if (o < COUT && l < LOUT)
                Y[((size_t)b * COUT + o) * LOUT + l] = fmaxf(acc[oo][ll] + bias[o], 0.f);
        }
    }
}

__global__ void k_pool3(const float* __restrict__ in, float* __restrict__ out,
                        int C, int LIN, int LOUT) {
    int idx = blockIdx.x * blockDim.x + threadIdx.x;
    int total = BB * C * LOUT;
    if (idx >= total) return;
    int l = idx % LOUT;
    int bc = idx / LOUT;
    const float* p = in + (size_t)bc * LIN + 2 * l;
    out[idx] = fmaxf(fmaxf(p[0], p[1]), p[2]);
}

// pool k=2 s=2, transposed + split bf16 with zero pads: out [(b*99+l), 2*KPAD]
__global__ void k_pool2t_split(const float* __restrict__ in, __nv_bfloat16* __restrict__ out,
                               int C, int LIN, int LOUT, int KPAD) {
    int idx = blockIdx.x * blockDim.x + threadIdx.x;
    int total = BB * LOUT * KPAD;
    if (idx >= total) return;
    int c = idx % KPAD;
    int l = (idx / KPAD) % LOUT;
    int b = idx / (KPAD * LOUT);
    size_t m = (size_t)b * LOUT + l;
    float v = 0.f;
    if (c < C) {
        const float* p = in + ((size_t)b * C + c) * LIN + 2 * l;
        v = fmaxf(p[0], p[1]);
    }
    __nv_bfloat16 hi, lo;
    split2(v, hi, lo);
    out[m * 2 * KPAD + c] = hi;
    out[m * 2 * KPAD + KPAD + c] = lo;
}

__global__ void k_transpose(const float* __restrict__ src, float* __restrict__ dst,
                            int Cs, int co, int Ctot) {
    __shared__ float t[32][33];
    int b = blockIdx.z;
    int l0 = blockIdx.x * 32, c0 = blockIdx.y * 32;
    int tx = threadIdx.x, ty = threadIdx.y;
#pragma unroll
    for (int i = 0; i < 4; i++) {
        int l = l0 + ty + i * 8, c = c0 + tx;
        if (l < LL && c < Cs)
            t[tx][ty + i * 8] = src[((size_t)b * LL + l) * Cs + c];
    }
    __syncthreads();
#pragma unroll
    for (int i = 0; i < 4; i++) {
        int c = c0 + ty + i * 8, l = l0 + tx;
        if (c < Cs && l < LL)
            dst[((size_t)b * Ctot + co + c) * LL + l] = t[ty + i * 8][tx];
    }
}

__global__ void k_avg(const float* __restrict__ yp, const float* __restrict__ zp,
                      float* __restrict__ avg) {
    int idx = blockIdx.x * blockDim.x + threadIdx.x;
    if (idx >= BB * 256) return;
    int j = idx & 255;
    int b = idx >> 8;
    float s = 0.f;
    for (int l = 0; l < 99; l++) {
        size_t off = ((size_t)b * 99 + l) * 256 + j;
        s += yp[off] * zp[off];
    }
    avg[idx] = s * (1.f / 99.f);
}

__global__ void k_pack(const float* __restrict__ logits, const float* __restrict__ hf,
                       float* __restrict__ out, int out_size) {
    int i = blockIdx.x * blockDim.x + threadIdx.x;
    if (i >= out_size) return;
    out[i] = (i < BB * 2) ? logits[i] : hf[i - BB * 2];
}

// ---------------- launcher ----------------
extern "C" void kernel_launch(void* const* d_in, const int* in_sizes, int n_in,
                              void* d_out, int out_size) {
    const float* x    = (const float*)d_in[0];
    const int*   eidx = (const int*)d_in[1];
    const int*   etyp = (const int*)d_in[2];
    const float* ggnnW = (const float*)d_in[3];
    const float* ggnnB = (const float*)d_in[4];
    const float* Wih  = (const float*)d_in[5];
    const float* Whh  = (const float*)d_in[6];
    const float* bih  = (const float*)d_in[7];
    const float* bhh  = (const float*)d_in[8];
    const float* c1w  = (const float*)d_in[9];
    const float* c1b  = (const float*)d_in[10];
    const float* c2w  = (const float*)d_in[11];
    const float* c2b  = (const float*)d_in[12];
    const float* cc1w = (const float*)d_in[13];
    const float* cc1b = (const float*)d_in[14];
    const float* cc2w = (const float*)d_in[15];
    const float* cc2b = (const float*)d_in[16];
    const float* yw   = (const float*)d_in[17];
    const float* yb   = (const float*)d_in[18];
    const float* zw   = (const float*)d_in[19];
    const float* zb   = (const float*)d_in[20];
    const float* l1w  = (const float*)d_in[21];
    const float* l1b  = (const float*)d_in[22];
    const float* f1w  = (const float*)d_in[23];
    const float* f1b  = (const float*)d_in[24];
    const float* f2w  = (const float*)d_in[25];
    const float* f2b  = (const float*)d_in[26];
    const float* clsw = (const float*)d_in[27];
    const float* clsb = (const float*)d_in[28];
    float* out = (float*)d_out;

    void* p;
#define GET(name, sym, T) cudaGetSymbolAddress(&p, sym); T* name = (T*)p;
    GET(h0, g_h0, float) GET(h1, g_h1, float)
    GET(h0s, g_h0s, __nv_bfloat16) GET(h1s, g_h1s, __nv_bfloat16)
    GET(ss, g_ss, __nv_bfloat16) GET(as, g_as, __nv_bfloat16)
    GET(gi, g_gi, float) GET(gh, g_gh, float)
    GET(cnt0, g_cnt0, int) GET(cnt1, g_cnt1, int)
    GET(rowptr, g_rowptr, int) GET(rowfill, g_rowfill, int) GET(colv, g_col, int)
    GET(wcs, g_wcat_s, __nv_bfloat16) GET(wis, g_wih_s, __nv_bfloat16) GET(whs, g_whh_s, __nv_bfloat16)
    GET(mys, g_myw_s, __nv_bfloat16) GET(mzs, g_mzw_s, __nv_bfloat16)
    GET(ht, g_ht, float) GET(ct, g_ct, float)
    GET(y1pre, g_y1pre, float) GET(y1, g_y1, float) GET(y2pre, g_y2pre, float)
    GET(y2ts, g_y2ts, __nv_bfloat16)
    GET(z1pre, g_z1pre, float) GET(z1, g_z1, float) GET(z2pre, g_z2pre, float)
    GET(z2ts, g_z2ts, __nv_bfloat16)
    GET(yp, g_yp, float) GET(zp, g_zp, float) GET(avg, g_avg, float)
    GET(m1, g_m1, float) GET(m2, g_m2, float) GET(hfv, g_hf, float) GET(logits, g_logits, float)
#undef GET

    const int SMEM = 2 * 128 * ROWB + 2 * 64 * ROWB;   // 55296
    cudaFuncSetAttribute(gemm_mma<448, 1>, cudaFuncAttributeMaxDynamicSharedMemorySize, SMEM);
    cudaFuncSetAttribute(gemm_mma<256, 0>, cudaFuncAttributeMaxDynamicSharedMemorySize, SMEM);
    cudaFuncSetAttribute(gemm_mma<320, 0>, cudaFuncAttributeMaxDynamicSharedMemorySize, SMEM);

    // preprocessing
    k_init_h<<<(NN * 256 + 255) / 256, 256>>>(x, h0, h0s);
    k_zero_cnt<<<(2 * NN + 255) / 256, 256>>>(cnt0, cnt1);
    k_count<<<EE / 256, 256>>>(eidx, etyp, cnt0, cnt1);
    k_scan<<<1, 1024>>>(cnt0, cnt1, rowptr, rowfill);
    k_fill<<<EE / 256, 256>>>(eidx, etyp, rowfill, colv);
    k_wcat_split<<<(200 * 448 + 255) / 256, 256>>>(ggnnW, wcs);
    k_split_w<<<(600 * 256 + 255) / 256, 256>>>(Wih, wis, 600, 200, 256);
    k_split_w<<<(600 * 256 + 255) / 256, 256>>>(Whh, whs, 600, 200, 256);
    k_split_w<<<(256 * 256 + 255) / 256, 256>>>(yw, mys, 256, 200, 256);
    k_split_w<<<(256 * 320 + 255) / 256, 256>>>(zw, mzs, 256, 320, 320);

    // GGNN steps
    for (int s = 0; s < NSTEPS; s++) {
        float* hin  = (s & 1) ? h1 : h0;
        float* hout = (s & 1) ? h0 : h1;
        __nv_bfloat16* hins  = (s & 1) ? h1s : h0s;
        __nv_bfloat16* houts = (s & 1) ? h0s : h1s;
        k_gather<<<NN / 8, 256>>>(hin, rowptr, colv, ss);
        gemm_mma<448, 1><<<dim3(4, NN / 128), 256, SMEM>>>(
            ss, 896, wcs, 896, 200, nullptr, 0, ggnnB, as, 256, cnt0, cnt1, ggnnB + 200);
        gemm_mma<256, 0><<<dim3(10, NN / 128), 256, SMEM>>>(
            as, 512, wis, 512, 600, gi, 600, bih, nullptr, 0, nullptr, nullptr, nullptr);
        gemm_mma<256, 0><<<dim3(10, NN / 128), 256, SMEM>>>(
            hins, 512, whs, 512, 600, gh, 600, bhh, nullptr, 0, nullptr, nullptr, nullptr);
        k_gru<<<(NN * 256 + 255) / 256, 256>>>(gi, gh, hin, hout, houts);
    }
    float* hfin = h0;

    // readout
    dim3 tb(32, 8);
    k_transpose<<<dim3(13, 7, BB), tb>>>(hfin, ht, HH, 0, HH);
    k_transpose<<<dim3(13, 4, BB), tb>>>(x, ct, DD, 0, CCC);
    k_transpose<<<dim3(13, 7, BB), tb>>>(hfin, ct, HH, DD, CCC);

    conv_relu<3><<<dim3(7, 4, BB), 256>>>(ht, c1w, c1b, y1pre, HH, HH, 400, 398);
    k_pool3<<<(BB * HH * 198 + 255) / 256, 256>>>(y1pre, y1, HH, 398, 198);
    conv_relu<1><<<dim3(4, 4, BB), 256>>>(y1, c2w, c2b, y2pre, HH, HH, 198, 198);
    k_pool2t_split<<<(BB * 99 * 256 + 255) / 256, 256>>>(y2pre, y2ts, HH, 198, 99, 256);

    conv_relu<3><<<dim3(7, 5, BB), 256>>>(ct, cc1w, cc1b, z1pre, CCC, CCC, 400, 398);
    k_pool3<<<(BB * CCC * 198 + 255) / 256, 256>>>(z1pre, z1, CCC, 398, 198);
    conv_relu<1><<<dim3(4, 5, BB), 256>>>(z1, cc2w, cc2b, z2pre, CCC, CCC, 198, 198);
    k_pool2t_split<<<(BB * 99 * 320 + 255) / 256, 256>>>(z2pre, z2ts, CCC, 198, 99, 320);

    gemm_mma<256, 0><<<dim3(4, M2 / 128), 256, SMEM>>>(
        y2ts, 512, mys, 512, 256, yp, 256, yb, nullptr, 0, nullptr, nullptr, nullptr);
    gemm_mma<320, 0><<<dim3(4, M2 / 128), 256, SMEM>>>(
        z2ts, 640, mzs, 640, 256, zp, 256, zb, nullptr, 0, nullptr, nullptr, nullptr);
    k_avg<<<(BB * 256 + 255) / 256, 256>>>(yp, zp, avg);

    gemm_tn<1><<<dim3(2, 2), 256>>>(avg, l1w, l1b, m1, BB, 128, 256);
    gemm_tn<1><<<dim3(1, 2), 256>>>(m1, f1w, f1b, m2, BB, 64, 128);
    gemm_tn<1><<<dim3(2, 2), 256>>>(m2, f2w, f2b, hfv, BB, 128, 64);
    gemm_tn<0><<<dim3(1, 2), 256>>>(hfv, clsw, clsb, logits, BB, 2, 128);

    k_pack<<<(out_size + 255) / 256, 256>>>(logits, hfv, out, out_size);
    (void)n_in; (void)in_sizes;
}

// round 4
// speedup vs baseline: 1.8945x; 1.3439x over previous
#include <cuda_runtime.h>
#include <cuda_bf16.h>
#include <math.h>
#include <stdint.h>

// ---------------- problem constants ----------------
#define NN 102400
#define EE 819200
#define DD 120
#define HH 200
#define CCC 320
#define LL 400
#define BB 256
#define NSTEPS 8
#define M2 25344          // BB*99
#define MP 50688          // BB*198

// ---------------- PTX helpers ----------------
__device__ __forceinline__ uint32_t smem_u32(const void* p) {
    uint32_t a;
    asm("{ .reg .u64 t; cvta.to.shared.u64 t, %1; cvt.u32.u64 %0, t; }" : "=r"(a) : "l"(p));
    return a;
}
#define CP_ASYNC16(dst, src) \
    asm volatile("cp.async.cg.shared.global [%0], [%1], 16;" :: "r"(dst), "l"(src) : "memory")
#define CP_ASYNC16Z(dst, src, sz) \
    asm volatile("cp.async.cg.shared.global [%0], [%1], 16, %2;" :: "r"(dst), "l"(src), "r"(sz) : "memory")
#define CP_COMMIT() asm volatile("cp.async.commit_group;" ::: "memory")
#define CP_WAIT(n)  asm volatile("cp.async.wait_group %0;" :: "n"(n) : "memory")
#define LDSM4(r, addr) \
    asm volatile("ldmatrix.sync.aligned.m8n8.x4.shared.b16 {%0,%1,%2,%3}, [%4];" \
        : "=r"((r)[0]), "=r"((r)[1]), "=r"((r)[2]), "=r"((r)[3]) : "r"(addr))
#define MMA16816(d, a, bx, by) \
    asm volatile("mma.sync.aligned.m16n8k16.row.col.f32.bf16.bf16.f32 " \
        "{%0,%1,%2,%3}, {%4,%5,%6,%7}, {%8,%9}, {%0,%1,%2,%3};" \
        : "+f"((d)[0]), "+f"((d)[1]), "+f"((d)[2]), "+f"((d)[3]) \
        : "r"((a)[0]), "r"((a)[1]), "r"((a)[2]), "r"((a)[3]), "r"(bx), "r"(by))

__device__ __forceinline__ void split2(float v, __nv_bfloat16& hi, __nv_bfloat16& lo) {
    hi = __float2bfloat16(v);
    lo = __float2bfloat16(v - __bfloat162float(hi));
}
__device__ __forceinline__ uint32_t packbf(__nv_bfloat16 a, __nv_bfloat16 b) {
    return (uint32_t)__bfloat16_as_ushort(a) | ((uint32_t)__bfloat16_as_ushort(b) << 16);
}

// ---------------- scratch ----------------
__device__ __align__(256) float g_h0[NN * HH];
__device__ __align__(256) float g_h1[NN * HH];
__device__ __align__(256) __nv_bfloat16 g_h0s[(NN + 2) * 512];
__device__ __align__(256) __nv_bfloat16 g_h1s[(NN + 2) * 512];
__device__ __align__(256) __nv_bfloat16 g_ss[NN * 896];
__device__ __align__(256) __nv_bfloat16 g_as[NN * 512];
__device__ __align__(256) float g_gi[NN * 600];
__device__ __align__(256) float g_gh[NN * 600];
__device__ int g_cnt[2 * NN];
__device__ int g_rowptr[2 * NN + 1];
__device__ int g_rowfill[2 * NN];
__device__ int g_col[EE];
__device__ int g_part[200];
__device__ int g_pref[200];

__device__ __align__(256) __nv_bfloat16 g_wcat_s[200 * 896];
__device__ __align__(256) __nv_bfloat16 g_wih_s[600 * 512];
__device__ __align__(256) __nv_bfloat16 g_whh_s[600 * 512];
__device__ __align__(256) __nv_bfloat16 g_myw_s[256 * 512];
__device__ __align__(256) __nv_bfloat16 g_mzw_s[256 * 640];
__device__ __align__(256) __nv_bfloat16 g_c1p[200 * 3 * 512];
__device__ __align__(256) __nv_bfloat16 g_c2p[200 * 512];
__device__ __align__(256) __nv_bfloat16 g_cc1p[320 * 3 * 640];
__device__ __align__(256) __nv_bfloat16 g_cc2p[320 * 640];

__device__ __align__(256) __nv_bfloat16 g_xcat[(NN + 2) * 640];
__device__ __align__(256) float g_y1g[NN * 200];
__device__ __align__(256) float g_z1g[NN * 320];
__device__ __align__(256) __nv_bfloat16 g_y1s[(MP + 2) * 512];
__device__ __align__(256) __nv_bfloat16 g_z1s[(MP + 2) * 640];
__device__ __align__(256) float g_y2g[MP * 200];
__device__ __align__(256) float g_z2g[MP * 320];
__device__ __align__(256) __nv_bfloat16 g_y2ps[M2 * 512];
__device__ __align__(256) __nv_bfloat16 g_z2ps[M2 * 640];
__device__ __align__(256) float g_yp[M2 * 256];
__device__ __align__(256) float g_zp[M2 * 256];
__device__ float g_avg[BB * 256];
__device__ float g_m1[BB * 128];
__device__ float g_m2[BB * 64];
__device__ float g_hf[BB * 128];
__device__ float g_logits[BB * 2];

// ---------------- HMMA split-bf16 GEMM (with conv row-shift support) -------
// C[M, Ncols] = sum over 3 numeric segments x NKW kernel taps.
// A: [rows, 2*KPAD] bf16 (hi|lo); conv taps read row m+kw (buffers have +2 pad rows).
// B: [Ncols, NKW*2*KPAD] bf16, tap kw at offset kw*2*KPAD, (hi|lo) within.
// EPI 0: C = v + bias[n] (fp32) | EPI 1: v += cc0[m]*bias[n]+cc1[m]*b1[n], split->OS
// EPI 2: C = relu(v + bias[n]) (fp32)
#define ROWB 144
template<int KPAD, int NKW, int EPI>
__global__ void __launch_bounds__(256, 2)
gemm_mma(const __nv_bfloat16* __restrict__ A, int lda,
         const __nv_bfloat16* __restrict__ Bw, int ldb, int Ncols,
         float* __restrict__ C, int ldc, const float* __restrict__ bias,
         __nv_bfloat16* __restrict__ OS, int okpad,
         const int* __restrict__ cc0, const int* __restrict__ cc1,
         const float* __restrict__ b1) {
    constexpr int CPS = KPAD / 64;
    constexpr int NCH = 3 * NKW * CPS;
    constexpr int ASTG = 128 * ROWB;
    constexpr int BBASE = 2 * ASTG;
    constexpr int BSTG = 64 * ROWB;
    extern __shared__ char smem[];
    const uint32_t sb = smem_u32(smem);
    const int tid = threadIdx.x, lane = tid & 31, wid = tid >> 5;
    const int m0 = blockIdx.y * 128, n0 = blockIdx.x * 64;
    const int wm = wid >> 1, wn = wid & 1;

    float acc[2][4][4];
#pragma unroll
    for (int i = 0; i < 2; i++)
#pragma unroll
        for (int j = 0; j < 4; j++)
#pragma unroll
            for (int k = 0; k < 4; k++) acc[i][j][k] = 0.f;

    auto load_stage = [&](int i, int st) {
        int seg = i / (NKW * CPS);
        int rem = i - seg * (NKW * CPS);
        int kw = rem / CPS;
        int c = rem - kw * CPS;
        int aoff = (seg == 1 ? KPAD : 0) + c * 64;
        int boff = kw * 2 * KPAD + (seg == 2 ? KPAD : 0) + c * 64;
        uint32_t sA = sb + st * ASTG;
        uint32_t sB = sb + BBASE + st * BSTG;
#pragma unroll
        for (int t = 0; t < 4; t++) {
            int idx = tid + t * 256;
            int row = idx >> 3, j = idx & 7;
            const __nv_bfloat16* src = A + (size_t)(m0 + row + kw) * lda + aoff + j * 8;
            CP_ASYNC16(sA + row * ROWB + j * 16, src);
        }
#pragma unroll
        for (int t = 0; t < 2; t++) {
            int idx = tid + t * 256;
            int row = idx >> 3, j = idx & 7;
            int n = n0 + row;
            int ok = (n < Ncols);
            const __nv_bfloat16* src = Bw + (size_t)(ok ? n : 0) * ldb + boff + j * 8;
            CP_ASYNC16Z(sB + row * ROWB + j * 16, src, ok ? 16 : 0);
        }
        CP_COMMIT();
    };

    const uint32_t aLane = (uint32_t)((wm * 32 + (lane & 15)) * ROWB + ((lane >> 4) * 8) * 2);
    const uint32_t bLane = (uint32_t)((wn * 32 + (lane & 7) + ((lane >> 4) * 8)) * ROWB +
                                      (((lane >> 3) & 1) * 8) * 2);

    load_stage(0, 0);
    for (int i = 0; i < NCH; i++) {
        int st = i & 1;
        if (i + 1 < NCH) { load_stage(i + 1, (i + 1) & 1); CP_WAIT(1); }
        else             { CP_WAIT(0); }
        __syncthreads();
        uint32_t aB = sb + st * ASTG + aLane;
        uint32_t bB = sb + BBASE + st * BSTG + bLane;
#pragma unroll
        for (int ks = 0; ks < 4; ks++) {
            uint32_t a0[4], a1[4], b0[4], b1v[4];
            LDSM4(a0, aB + ks * 32);
            LDSM4(a1, aB + 16 * ROWB + ks * 32);
            LDSM4(b0, bB + ks * 32);
            LDSM4(b1v, bB + 16 * ROWB + ks * 32);
            MMA16816(acc[0][0], a0, b0[0], b0[1]);
            MMA16816(acc[0][1], a0, b0[2], b0[3]);
            MMA16816(acc[0][2], a0, b1v[0], b1v[1]);
            MMA16816(acc[0][3], a0, b1v[2], b1v[3]);
            MMA16816(acc[1][0], a1, b0[0], b0[1]);
            MMA16816(acc[1][1], a1, b0[2], b0[3]);
            MMA16816(acc[1][2], a1, b1v[0], b1v[1]);
            MMA16816(acc[1][3], a1, b1v[2], b1v[3]);
        }
        __syncthreads();
    }

    const int g = lane >> 2, tg = lane & 3;
#pragma unroll
    for (int mi = 0; mi < 2; mi++) {
        int mA = m0 + wm * 32 + mi * 16 + g;
#pragma unroll
        for (int nj = 0; nj < 4; nj++) {
            int n = n0 + wn * 32 + nj * 8 + tg * 2;
            float v0 = acc[mi][nj][0], v1 = acc[mi][nj][1];
            float v2 = acc[mi][nj][2], v3 = acc[mi][nj][3];
            if (EPI == 0 || EPI == 2) {
                if (n < Ncols) {
                    float bn = bias[n], bn1 = bias[n + 1];
                    v0 += bn; v1 += bn1; v2 += bn; v3 += bn1;
                    if (EPI == 2) {
                        v0 = fmaxf(v0, 0.f); v1 = fmaxf(v1, 0.f);
                        v2 = fmaxf(v2, 0.f); v3 = fmaxf(v3, 0.f);
                    }
                    *(float2*)&C[(size_t)mA * ldc + n] = make_float2(v0, v1);
                    *(float2*)&C[(size_t)(mA + 8) * ldc + n] = make_float2(v2, v3);
                }
            } else {
                uint32_t hi0 = 0, lo0 = 0, hi1 = 0, lo1 = 0;
                if (n < Ncols) {
                    float bn = bias[n], bn1 = bias[n + 1];
                    float dn = b1[n], dn1 = b1[n + 1];
                    float q0a = (float)cc0[mA], q1a = (float)cc1[mA];
                    float q0b = (float)cc0[mA + 8], q1b = (float)cc1[mA + 8];
                    v0 += q0a * bn + q1a * dn;   v1 += q0a * bn1 + q1a * dn1;
                    v2 += q0b * bn + q1b * dn;   v3 += q0b * bn1 + q1b * dn1;
                    __nv_bfloat16 h0, l0, h1, l1;
                    split2(v0, h0, l0); split2(v1, h1, l1);
                    hi0 = packbf(h0, h1); lo0 = packbf(l0, l1);
                    split2(v2, h0, l0); split2(v3, h1, l1);
                    hi1 = packbf(h0, h1); lo1 = packbf(l0, l1);
                }
                if (n < okpad) {
                    *(uint32_t*)&OS[(size_t)mA * (2 * okpad) + n] = hi0;
                    *(uint32_t*)&OS[(size_t)mA * (2 * okpad) + okpad + n] = lo0;
                    *(uint32_t*)&OS[(size_t)(mA + 8) * (2 * okpad) + n] = hi1;
                    *(uint32_t*)&OS[(size_t)(mA + 8) * (2 * okpad) + okpad + n] = lo1;
                }
            }
        }
    }
}

// ---------------- preprocessing kernels ----------------
__global__ void k_init_h(const float* __restrict__ x, float* __restrict__ h,
                         __nv_bfloat16* __restrict__ hs0, __nv_bfloat16* __restrict__ hs1) {
    int idx = blockIdx.x * blockDim.x + threadIdx.x;
    if (idx >= (NN + 2) * 256) return;
    int n = idx >> 8, c = idx & 255;
    __nv_bfloat16 z = __float2bfloat16(0.f);
    if (n >= NN) {
        hs0[(size_t)n * 512 + c] = z;      hs0[(size_t)n * 512 + 256 + c] = z;
        hs1[(size_t)n * 512 + c] = z;      hs1[(size_t)n * 512 + 256 + c] = z;
        return;
    }
    float v = (c < DD) ? x[(size_t)n * DD + c] : 0.f;
    if (c < HH) h[(size_t)n * HH + c] = v;
    __nv_bfloat16 hi, lo;
    split2(v, hi, lo);
    hs0[(size_t)n * 512 + c] = hi;
    hs0[(size_t)n * 512 + 256 + c] = lo;
}

__global__ void k_zero_cnt(int* __restrict__ c) {
    int idx = blockIdx.x * blockDim.x + threadIdx.x;
    if (idx < 2 * NN) c[idx] = 0;
}

__global__ void k_count(const int* __restrict__ eidx, const int* __restrict__ etyp,
                        int* __restrict__ cnt) {
    int e = blockIdx.x * blockDim.x + threadIdx.x;
    if (e >= EE) return;
    int d = eidx[EE + e] + (etyp[e] ? NN : 0);
    atomicAdd(&cnt[d], 1);
}

__global__ void k_scan1(const int* __restrict__ cnt, int* __restrict__ part) {
    __shared__ int sh[1024];
    int t = threadIdx.x;
    int v = cnt[blockIdx.x * 1024 + t];
    sh[t] = v;
    __syncthreads();
    for (int off = 512; off > 0; off >>= 1) {
        if (t < off) sh[t] += sh[t + off];
        __syncthreads();
    }
    if (t == 0) part[blockIdx.x] = sh[0];
}

__global__ void k_scan2(const int* __restrict__ part, int* __restrict__ pref,
                        int* __restrict__ rowptr) {
    __shared__ int sh[256];
    int t = threadIdx.x;
    int v = (t < 200) ? part[t] : 0;
    sh[t] = v;
    __syncthreads();
    for (int off = 1; off < 256; off <<= 1) {
        int u = (t >= off) ? sh[t - off] : 0;
        __syncthreads();
        sh[t] += u;
        __syncthreads();
    }
    if (t < 200) pref[t] = sh[t] - v;
    if (t == 0) rowptr[2 * NN] = EE;
}

__global__ void k_scan3(const int* __restrict__ cnt, const int* __restrict__ pref,
                        int* __restrict__ rowptr, int* __restrict__ rowfill) {
    __shared__ int sh[1024];
    int t = threadIdx.x;
    int i = blockIdx.x * 1024 + t;
    int v = cnt[i];
    sh[t] = v;
    __syncthreads();
    for (int off = 1; off < 1024; off <<= 1) {
        int u = (t >= off) ? sh[t - off] : 0;
        __syncthreads();
        sh[t] += u;
        __syncthreads();
    }
    int excl = sh[t] - v + pref[blockIdx.x];
    rowptr[i] = excl;
    rowfill[i] = excl;
}

__global__ void k_fill(const int* __restrict__ eidx, const int* __restrict__ etyp,
                       int* __restrict__ rowfill, int* __restrict__ col) {
    int e = blockIdx.x * blockDim.x + threadIdx.x;
    if (e >= EE) return;
    int d = eidx[EE + e] + (etyp[e] ? NN : 0);
    int p = atomicAdd(&rowfill[d], 1);
    col[p] = eidx[e];
}

// generic weight pack: src [O, I, KW] -> dst [O, KW*2*KPAD] split bf16 zero-padded
__global__ void k_packw(const float* __restrict__ src, __nv_bfloat16* __restrict__ dst,
                        int O, int I, int KW, int KPAD) {
    int idx = blockIdx.x * blockDim.x + threadIdx.x;
    if (idx >= O * KW * KPAD) return;
    int o = idx / (KW * KPAD);
    int r = idx % (KW * KPAD);
    int kw = r / KPAD, c = r % KPAD;
    float v = (c < I) ? src[((size_t)o * I + c) * KW + kw] : 0.f;
    __nv_bfloat16 hi, lo;
    split2(v, hi, lo);
    size_t base = (size_t)o * (KW * 2 * KPAD) + (size_t)kw * 2 * KPAD;
    dst[base + c] = hi;
    dst[base + KPAD + c] = lo;
}

__global__ void k_wcat_split(const float* __restrict__ gW, __nv_bfloat16* __restrict__ dst) {
    int idx = blockIdx.x * blockDim.x + threadIdx.x;
    if (idx >= 200 * 448) return;
    int o = idx / 448, k = idx % 448;
    float v = 0.f;
    if (k < 200)      v = gW[(size_t)o * 200 + k];
    else if (k < 400) v = gW[(size_t)200 * 200 + (size_t)o * 200 + (k - 200)];
    __nv_bfloat16 hi, lo;
    split2(v, hi, lo);
    dst[(size_t)o * 896 + k] = hi;
    dst[(size_t)o * 896 + 448 + k] = lo;
}

// ---------------- gather: warp per (node, etype) ----------------
__global__ void k_gather(const float* __restrict__ h, const int* __restrict__ rowptr,
                         const int* __restrict__ col, __nv_bfloat16* __restrict__ s) {
    int warp = (blockIdx.x * blockDim.x + threadIdx.x) >> 5;
    int lane = threadIdx.x & 31;
    if (warp >= 2 * NN) return;
    int node = (warp < NN) ? warp : warp - NN;
    int ty   = (warp < NN) ? 0 : 1;
    float a[7];
#pragma unroll
    for (int i = 0; i < 7; i++) a[i] = 0.f;
    int beg = rowptr[warp], end = rowptr[warp + 1];
    for (int e = beg; e < end; e++) {
        const float* hr = h + (size_t)col[e] * HH;
#pragma unroll
        for (int i = 0; i < 7; i++) {
            int c = lane + i * 32;
            if (c < HH) a[i] += __ldg(hr + c);
        }
    }
    __nv_bfloat16* sr = s + (size_t)node * 896;
#pragma unroll
    for (int i = 0; i < 7; i++) {
        int c = lane + i * 32;
        if (c < HH) {
            __nv_bfloat16 hi, lo;
            split2(a[i], hi, lo);
            sr[ty * 200 + c] = hi;
            sr[448 + ty * 200 + c] = lo;
        }
    }
    if (ty == 1) {
        __nv_bfloat16 z = __float2bfloat16(0.f);
        for (int c = 400 + lane; c < 448; c += 32) { sr[c] = z; sr[448 + c] = z; }
    }
}

__global__ void k_gru(const float* __restrict__ gi, const float* __restrict__ gh,
                      const float* __restrict__ h, float* __restrict__ hn,
                      __nv_bfloat16* __restrict__ hns) {
    int idx = blockIdx.x * blockDim.x + threadIdx.x;
    if (idx >= NN * 256) return;
    int n = idx >> 8, c = idx & 255;
    __nv_bfloat16* hp = hns + (size_t)n * 512;
    if (c >= HH) {
        __nv_bfloat16 z = __float2bfloat16(0.f);
        hp[c] = z; hp[256 + c] = z;
        return;
    }
    size_t base = (size_t)n * (3 * HH) + c;
    float ir = gi[base], iz = gi[base + HH], inn = gi[base + 2 * HH];
    float hr = gh[base], hz = gh[base + HH], hnn = gh[base + 2 * HH];
    float r = 1.f / (1.f + expf(-(ir + hr)));
    float z = 1.f / (1.f + expf(-(iz + hz)));
    float nv = tanhf(inn + r * hnn);
    float v = (1.f - z) * nv + z * h[(size_t)n * HH + c];
    hn[(size_t)n * HH + c] = v;
    __nv_bfloat16 hi, lo;
    split2(v, hi, lo);
    hp[c] = hi;
    hp[256 + c] = lo;
}

// concat(x, h) -> split bf16 [NN+2, 2*320]
__global__ void k_catsplit(const float* __restrict__ x, const float* __restrict__ h,
                           __nv_bfloat16* __restrict__ dst) {
    int idx = blockIdx.x * blockDim.x + threadIdx.x;
    if (idx >= (NN + 2) * 320) return;
    int n = idx / 320, c = idx % 320;
    float v = 0.f;
    if (n < NN) v = (c < DD) ? x[(size_t)n * DD + c] : h[(size_t)n * HH + (c - DD)];
    __nv_bfloat16 hi, lo;
    split2(v, hi, lo);
    dst[(size_t)n * 640 + c] = hi;
    dst[(size_t)n * 640 + 320 + c] = lo;
}

// pool k=3 s=2 over conv rows [b*400+l, C] -> split bf16 [b*198+l', 2*KPAD] (+2 pad rows)
__global__ void k_pool3s(const float* __restrict__ in, __nv_bfloat16* __restrict__ out,
                         int C, int KPAD) {
    int idx = blockIdx.x * blockDim.x + threadIdx.x;
    if (idx >= (MP + 2) * KPAD) return;
    int m = idx / KPAD, c = idx % KPAD;
    float v = 0.f;
    if (m < MP && c < C) {
        int b = m / 198, l = m % 198;
        size_t base = ((size_t)b * 400 + 2 * l) * C + c;
        v = fmaxf(fmaxf(in[base], in[base + C]), in[base + 2 * C]);
    }
    __nv_bfloat16 hi, lo;
    split2(v, hi, lo);
    out[(size_t)m * 2 * KPAD + c] = hi;
    out[(size_t)m * 2 * KPAD + KPAD + c] = lo;
}

// pool k=2 s=2 over rows [b*198+l, C] -> split bf16 [b*99+l', 2*KPAD]
__global__ void k_pool2s(const float* __restrict__ in, __nv_bfloat16* __restrict__ out,
                         int C, int KPAD) {
    int idx = blockIdx.x * blockDim.x + threadIdx.x;
    if (idx >= M2 * KPAD) return;
    int m = idx / KPAD, c = idx % KPAD;
    float v = 0.f;
    if (c < C) {
        int b = m / 99, l = m % 99;
        size_t base = ((size_t)b * 198 + 2 * l) * C + c;
        v = fmaxf(in[base], in[base + C]);
    }
    __nv_bfloat16 hi, lo;
    split2(v, hi, lo);
    out[(size_t)m * 2 * KPAD + c] = hi;
    out[(size_t)m * 2 * KPAD + KPAD + c] = lo;
}

__global__ void k_avg(const float* __restrict__ yp, const float* __restrict__ zp,
                      float* __restrict__ avg) {
    int idx = blockIdx.x * blockDim.x + threadIdx.x;
    if (idx >= BB * 256) return;
    int j = idx & 255;
    int b = idx >> 8;
    float s = 0.f;
    for (int l = 0; l < 99; l++) {
        size_t off = ((size_t)b * 99 + l) * 256 + j;
        s += yp[off] * zp[off];
    }
    avg[idx] = s * (1.f / 99.f);
}

// ---------------- tiny SIMT head GEMM ----------------
template<int EPI>
__global__ __launch_bounds__(256)
void gemm_tn(const float* __restrict__ A, const float* __restrict__ W,
             const float* __restrict__ bias, float* __restrict__ C,
             int M, int Nc, int K) {
    __shared__ float As[8][128];
    __shared__ float Ws[8][64];
    int tid = threadIdx.x;
    int m0 = blockIdx.y * 128;
    int n0 = blockIdx.x * 64;
    int msub = (tid >> 4) * 8;
    int nsub = (tid & 15) * 4;
    float acc[8][4];
#pragma unroll
    for (int i = 0; i < 8; i++)
#pragma unroll
        for (int j = 0; j < 4; j++) acc[i][j] = 0.f;
    int la_m = tid >> 1;
    int la_k = (tid & 1) * 4;
    int lw_n = tid >> 2;
    int lw_k = (tid & 3) * 2;
    for (int k0 = 0; k0 < K; k0 += 8) {
        float4 av = *(const float4*)(A + (size_t)(m0 + la_m) * K + k0 + la_k);
        As[la_k + 0][la_m] = av.x;
        As[la_k + 1][la_m] = av.y;
        As[la_k + 2][la_m] = av.z;
        As[la_k + 3][la_m] = av.w;
        float2 wv = make_float2(0.f, 0.f);
        if (n0 + lw_n < Nc)
            wv = *(const float2*)(W + (size_t)(n0 + lw_n) * K + k0 + lw_k);
        Ws[lw_k + 0][lw_n] = wv.x;
        Ws[lw_k + 1][lw_n] = wv.y;
        __syncthreads();
#pragma unroll
        for (int k = 0; k < 8; k++) {
            float4 a0 = *(const float4*)&As[k][msub];
            float4 a1 = *(const float4*)&As[k][msub + 4];
            float4 bv = *(const float4*)&Ws[k][nsub];
            float am[8] = {a0.x, a0.y, a0.z, a0.w, a1.x, a1.y, a1.z, a1.w};
            float bn[4] = {bv.x, bv.y, bv.z, bv.w};
#pragma unroll
            for (int i = 0; i < 8; i++)
#pragma unroll
                for (int j = 0; j < 4; j++) acc[i][j] += am[i] * bn[j];
        }
        __syncthreads();
    }
#pragma unroll
    for (int i = 0; i < 8; i++) {
        int m = m0 + msub + i;
#pragma unroll
        for (int j = 0; j < 4; j++) {
            int n = n0 + nsub + j;
            if (n < Nc) {
                float v = acc[i][j] + bias[n];
                if (EPI == 1) v = fmaxf(v, 0.f);
                C[(size_t)m * Nc + n] = v;
            }
        }
    }
}

__global__ void k_pack(const float* __restrict__ logits, const float* __restrict__ hf,
                       float* __restrict__ out, int out_size) {
    int i = blockIdx.x * blockDim.x + threadIdx.x;
    if (i >= out_size) return;
    out[i] = (i < BB * 2) ? logits[i] : hf[i - BB * 2];
}

// ---------------- launcher ----------------
extern "C" void kernel_launch(void* const* d_in, const int* in_sizes, int n_in,
                              void* d_out, int out_size) {
    const float* x    = (const float*)d_in[0];
    const int*   eidx = (const int*)d_in[1];
    const int*   etyp = (const int*)d_in[2];
    const float* ggnnW = (const float*)d_in[3];
    const float* ggnnB = (const float*)d_in[4];
    const float* Wih  = (const float*)d_in[5];
    const float* Whh  = (const float*)d_in[6];
    const float* bih  = (const float*)d_in[7];
    const float* bhh  = (const float*)d_in[8];
    const float* c1w  = (const float*)d_in[9];
    const float* c1b  = (const float*)d_in[10];
    const float* c2w  = (const float*)d_in[11];
    const float* c2b  = (const float*)d_in[12];
    const float* cc1w = (const float*)d_in[13];
    const float* cc1b = (const float*)d_in[14];
    const float* cc2w = (const float*)d_in[15];
    const float* cc2b = (const float*)d_in[16];
    const float* yw   = (const float*)d_in[17];
    const float* yb   = (const float*)d_in[18];
    const float* zw   = (const float*)d_in[19];
    const float* zb   = (const float*)d_in[20];
    const float* l1w  = (const float*)d_in[21];
    const float* l1b  = (const float*)d_in[22];
    const float* f1w  = (const float*)d_in[23];
    const float* f1b  = (const float*)d_in[24];
    const float* f2w  = (const float*)d_in[25];
    const float* f2b  = (const float*)d_in[26];
    const float* clsw = (const float*)d_in[27];
    const float* clsb = (const float*)d_in[28];
    float* out = (float*)d_out;

    void* p;
#define GET(name, sym, T) cudaGetSymbolAddress(&p, sym); T* name = (T*)p;
    GET(h0, g_h0, float) GET(h1, g_h1, float)
    GET(h0s, g_h0s, __nv_bfloat16) GET(h1s, g_h1s, __nv_bfloat16)
    GET(ss, g_ss, __nv_bfloat16) GET(as, g_as, __nv_bfloat16)
    GET(gi, g_gi, float) GET(gh, g_gh, float)
    GET(cnt, g_cnt, int) GET(rowptr, g_rowptr, int) GET(rowfill, g_rowfill, int)
    GET(colv, g_col, int) GET(part, g_part, int) GET(pref, g_pref, int)
    GET(wcs, g_wcat_s, __nv_bfloat16) GET(wis, g_wih_s, __nv_bfloat16) GET(whs, g_whh_s, __nv_bfloat16)
    GET(mys, g_myw_s, __nv_bfloat16) GET(mzs, g_mzw_s, __nv_bfloat16)
    GET(c1p, g_c1p, __nv_bfloat16) GET(c2p, g_c2p, __nv_bfloat16)
    GET(cc1p, g_cc1p, __nv_bfloat16) GET(cc2p, g_cc2p, __nv_bfloat16)
    GET(xcat, g_xcat, __nv_bfloat16)
    GET(y1g, g_y1g, float) GET(z1g, g_z1g, float)
    GET(y1s, g_y1s, __nv_bfloat16) GET(z1s, g_z1s, __nv_bfloat16)
    GET(y2g, g_y2g, float) GET(z2g, g_z2g, float)
    GET(y2ps, g_y2ps, __nv_bfloat16) GET(z2ps, g_z2ps, __nv_bfloat16)
    GET(yp, g_yp, float) GET(zp, g_zp, float) GET(avg, g_avg, float)
    GET(m1, g_m1, float) GET(m2v, g_m2, float) GET(hfv, g_hf, float) GET(logits, g_logits, float)
#undef GET

    const int SMEM = 2 * 128 * ROWB + 2 * 64 * ROWB;   // 55296
    cudaFuncSetAttribute(gemm_mma<448, 1, 1>, cudaFuncAttributeMaxDynamicSharedMemorySize, SMEM);
    cudaFuncSetAttribute(gemm_mma<256, 1, 0>, cudaFuncAttributeMaxDynamicSharedMemorySize, SMEM);
    cudaFuncSetAttribute(gemm_mma<256, 3, 2>, cudaFuncAttributeMaxDynamicSharedMemorySize, SMEM);
    cudaFuncSetAttribute(gemm_mma<256, 1, 2>, cudaFuncAttributeMaxDynamicSharedMemorySize, SMEM);
    cudaFuncSetAttribute(gemm_mma<320, 3, 2>, cudaFuncAttributeMaxDynamicSharedMemorySize, SMEM);
    cudaFuncSetAttribute(gemm_mma<320, 1, 2>, cudaFuncAttributeMaxDynamicSharedMemorySize, SMEM);
    cudaFuncSetAttribute(gemm_mma<320, 1, 0>, cudaFuncAttributeMaxDynamicSharedMemorySize, SMEM);

    // ---- preprocessing ----
    k_init_h<<<((NN + 2) * 256 + 255) / 256, 256>>>(x, h0, h0s, h1s);
    k_zero_cnt<<<(2 * NN + 255) / 256, 256>>>(cnt);
    k_count<<<EE / 256, 256>>>(eidx, etyp, cnt);
    k_scan1<<<200, 1024>>>(cnt, part);
    k_scan2<<<1, 256>>>(part, pref, rowptr);
    k_scan3<<<200, 1024>>>(cnt, pref, rowptr, rowfill);
    k_fill<<<EE / 256, 256>>>(eidx, etyp, rowfill, colv);
    k_wcat_split<<<(200 * 448 + 255) / 256, 256>>>(ggnnW, wcs);
    k_packw<<<(600 * 256 + 255) / 256, 256>>>(Wih, wis, 600, 200, 1, 256);
    k_packw<<<(600 * 256 + 255) / 256, 256>>>(Whh, whs, 600, 200, 1, 256);
    k_packw<<<(256 * 256 + 255) / 256, 256>>>(yw, mys, 256, 200, 1, 256);
    k_packw<<<(256 * 320 + 255) / 256, 256>>>(zw, mzs, 256, 320, 1, 320);
    k_packw<<<(200 * 3 * 256 + 255) / 256, 256>>>(c1w, c1p, 200, 200, 3, 256);
    k_packw<<<(200 * 256 + 255) / 256, 256>>>(c2w, c2p, 200, 200, 1, 256);
    k_packw<<<(320 * 3 * 320 + 255) / 256, 256>>>(cc1w, cc1p, 320, 320, 3, 320);
    k_packw<<<(320 * 320 + 255) / 256, 256>>>(cc2w, cc2p, 320, 320, 1, 320);

    // ---- GGNN steps ----
    for (int s = 0; s < NSTEPS; s++) {
        float* hin  = (s & 1) ? h1 : h0;
        float* hout = (s & 1) ? h0 : h1;
        __nv_bfloat16* hins  = (s & 1) ? h1s : h0s;
        __nv_bfloat16* houts = (s & 1) ? h0s : h1s;
        k_gather<<<2 * NN / 8, 256>>>(hin, rowptr, colv, ss);
        gemm_mma<448, 1, 1><<<dim3(4, NN / 128), 256, SMEM>>>(
            ss, 896, wcs, 896, 200, nullptr, 0, ggnnB, as, 256, cnt, cnt + NN, ggnnB + 200);
        gemm_mma<256, 1, 0><<<dim3(10, NN / 128), 256, SMEM>>>(
            as, 512, wis, 512, 600, gi, 600, bih, nullptr, 0, nullptr, nullptr, nullptr);
        gemm_mma<256, 1, 0><<<dim3(10, NN / 128), 256, SMEM>>>(
            hins, 512, whs, 512, 600, gh, 600, bhh, nullptr, 0, nullptr, nullptr, nullptr);
        k_gru<<<(NN * 256 + 255) / 256, 256>>>(gi, gh, hin, hout, houts);
    }
    // final h in h0 / h0s

    // ---- readout (all HMMA) ----
    k_catsplit<<<((NN + 2) * 320 + 255) / 256, 256>>>(x, h0, xcat);

    gemm_mma<256, 3, 2><<<dim3(4, NN / 128), 256, SMEM>>>(
        h0s, 512, c1p, 1536, 200, y1g, 200, c1b, nullptr, 0, nullptr, nullptr, nullptr);
    k_pool3s<<<((MP + 2) * 256 + 255) / 256, 256>>>(y1g, y1s, 200, 256);
    gemm_mma<256, 1, 2><<<dim3(4, MP / 128), 256, SMEM>>>(
        y1s, 512, c2p, 512, 200, y2g, 200, c2b, nullptr, 0, nullptr, nullptr, nullptr);
    k_pool2s<<<(M2 * 256 + 255) / 256, 256>>>(y2g, y2ps, 200, 256);

    gemm_mma<320, 3, 2><<<dim3(5, NN / 128), 256, SMEM>>>(
        xcat, 640, cc1p, 1920, 320, z1g, 320, cc1b, nullptr, 0, nullptr, nullptr, nullptr);
    k_pool3s<<<((MP + 2) * 320 + 255) / 256, 256>>>(z1g, z1s, 320, 320);
    gemm_mma<320, 1, 2><<<dim3(5, MP / 128), 256, SMEM>>>(
        z1s, 640, cc2p, 640, 320, z2g, 320, cc2b, nullptr, 0, nullptr, nullptr, nullptr);
    k_pool2s<<<(M2 * 320 + 255) / 256, 256>>>(z2g, z2ps, 320, 320);

    gemm_mma<256, 1, 0><<<dim3(4, M2 / 128), 256, SMEM>>>(
        y2ps, 512, mys, 512, 256, yp, 256, yb, nullptr, 0, nullptr, nullptr, nullptr);
    gemm_mma<320, 1, 0><<<dim3(4, M2 / 128), 256, SMEM>>>(
        z2ps, 640, mzs, 640, 256, zp, 256, zb, nullptr, 0, nullptr, nullptr, nullptr);
    k_avg<<<(BB * 256 + 255) / 256, 256>>>(yp, zp, avg);

    gemm_tn<1><<<dim3(2, 2), 256>>>(avg, l1w, l1b, m1, BB, 128, 256);
    gemm_tn<1><<<dim3(1, 2), 256>>>(m1, f1w, f1b, m2v, BB, 64, 128);
    gemm_tn<1><<<dim3(2, 2), 256>>>(m2v, f2w, f2b, hfv, BB, 128, 64);
    gemm_tn<0><<<dim3(1, 2), 256>>>(hfv, clsw, clsb, logits, BB, 2, 128);

    k_pack<<<(out_size + 255) / 256, 256>>>(logits, hfv, out, out_size);
    (void)n_in; (void)in_sizes;
}

// round 5
// speedup vs baseline: 2.0885x; 1.1024x over previous
#include <cuda_runtime.h>
#include <cuda_bf16.h>
#include <math.h>
#include <stdint.h>

// ---------------- problem constants ----------------
#define NN 102400
#define EE 819200
#define DD 120
#define HH 200
#define CCC 320
#define LL 400
#define BB 256
#define NSTEPS 8
#define M2 25344          // BB*99
#define MP 50688          // BB*198

// ---------------- PTX helpers ----------------
__device__ __forceinline__ uint32_t smem_u32(const void* p) {
    uint32_t a;
    asm("{ .reg .u64 t; cvta.to.shared.u64 t, %1; cvt.u32.u64 %0, t; }" : "=r"(a) : "l"(p));
    return a;
}
#define CP_ASYNC16(dst, src) \
    asm volatile("cp.async.cg.shared.global [%0], [%1], 16;" :: "r"(dst), "l"(src) : "memory")
#define CP_ASYNC16Z(dst, src, sz) \
    asm volatile("cp.async.cg.shared.global [%0], [%1], 16, %2;" :: "r"(dst), "l"(src), "r"(sz) : "memory")
#define CP_COMMIT() asm volatile("cp.async.commit_group;" ::: "memory")
#define CP_WAIT(n)  asm volatile("cp.async.wait_group %0;" :: "n"(n) : "memory")
#define LDSM4(r, addr) \
    asm volatile("ldmatrix.sync.aligned.m8n8.x4.shared.b16 {%0,%1,%2,%3}, [%4];" \
        : "=r"((r)[0]), "=r"((r)[1]), "=r"((r)[2]), "=r"((r)[3]) : "r"(addr))
#define MMA16816(d, a, bx, by) \
    asm volatile("mma.sync.aligned.m16n8k16.row.col.f32.bf16.bf16.f32 " \
        "{%0,%1,%2,%3}, {%4,%5,%6,%7}, {%8,%9}, {%0,%1,%2,%3};" \
        : "+f"((d)[0]), "+f"((d)[1]), "+f"((d)[2]), "+f"((d)[3]) \
        : "r"((a)[0]), "r"((a)[1]), "r"((a)[2]), "r"((a)[3]), "r"(bx), "r"(by))

__device__ __forceinline__ void split2(float v, __nv_bfloat16& hi, __nv_bfloat16& lo) {
    hi = __float2bfloat16(v);
    lo = __float2bfloat16(v - __bfloat162float(hi));
}
__device__ __forceinline__ uint32_t packbf(__nv_bfloat16 a, __nv_bfloat16 b) {
    return (uint32_t)__bfloat16_as_ushort(a) | ((uint32_t)__bfloat16_as_ushort(b) << 16);
}

// ---------------- scratch ----------------
__device__ __align__(256) float g_h0[NN * HH];
__device__ __align__(256) float g_h1[NN * HH];
__device__ __align__(256) __nv_bfloat16 g_h0s[(NN + 2) * 512];
__device__ __align__(256) __nv_bfloat16 g_h1s[(NN + 2) * 512];
__device__ __align__(256) __nv_bfloat16 g_ss[NN * 896];
__device__ __align__(256) __nv_bfloat16 g_as[NN * 512];
__device__ __align__(256) float g_gi[NN * 600];
__device__ __align__(256) float g_gh[NN * 600];
__device__ int g_cnt[2 * NN];
__device__ int g_rowptr[2 * NN + 1];
__device__ int g_rowfill[2 * NN];
__device__ int g_col[EE];
__device__ int g_part[200];
__device__ int g_pref[200];

__device__ __align__(256) __nv_bfloat16 g_wcat_s[200 * 896];
__device__ __align__(256) __nv_bfloat16 g_wih_s[600 * 512];
__device__ __align__(256) __nv_bfloat16 g_whh_s[600 * 512];
__device__ __align__(256) __nv_bfloat16 g_myw_s[256 * 512];
__device__ __align__(256) __nv_bfloat16 g_mzw_s[256 * 640];
__device__ __align__(256) __nv_bfloat16 g_c1p[200 * 3 * 512];
__device__ __align__(256) __nv_bfloat16 g_c2p[200 * 512];
__device__ __align__(256) __nv_bfloat16 g_cc1p[320 * 3 * 640];
__device__ __align__(256) __nv_bfloat16 g_cc2p[320 * 640];

__device__ __align__(256) __nv_bfloat16 g_xcat[(NN + 2) * 640];
__device__ __align__(256) float g_y1g[NN * 200];
__device__ __align__(256) float g_z1g[NN * 320];
__device__ __align__(256) __nv_bfloat16 g_y1s[(MP + 2) * 512];
__device__ __align__(256) __nv_bfloat16 g_z1s[(MP + 2) * 640];
__device__ __align__(256) float g_y2g[MP * 200];
__device__ __align__(256) float g_z2g[MP * 320];
__device__ __align__(256) __nv_bfloat16 g_y2ps[M2 * 512];
__device__ __align__(256) __nv_bfloat16 g_z2ps[M2 * 640];
__device__ __align__(256) float g_yp[M2 * 256];
__device__ __align__(256) float g_zp[M2 * 256];
__device__ float g_avg[BB * 256];
__device__ float g_m1[BB * 128];
__device__ float g_m2[BB * 64];
__device__ float g_hf[BB * 128];
__device__ float g_logits[BB * 2];

// ---------------- HMMA split-bf16 GEMM, 128x128 tile ----------------
// C[M, Ncols] = sum over 3 numeric segments x NKW conv taps.
// A: [rows, 2*KPAD] bf16 (hi|lo); conv taps read row m+kw (+2 pad rows in buffers).
// B: [Ncols, NKW*2*KPAD] bf16, tap kw at offset kw*2*KPAD.
// EPI 0: C = v + bias[n] | EPI 1: v += cc0[m]*bias[n]+cc1[m]*b1[n], split->OS
// EPI 2: C = relu(v + bias[n])
#define ROWB 144
template<int KPAD, int NKW, int EPI>
__global__ void __launch_bounds__(256, 2)
gemm_mma(const __nv_bfloat16* __restrict__ A, int lda,
         const __nv_bfloat16* __restrict__ Bw, int ldb, int Ncols,
         float* __restrict__ C, int ldc, const float* __restrict__ bias,
         __nv_bfloat16* __restrict__ OS, int okpad,
         const int* __restrict__ cc0, const int* __restrict__ cc1,
         const float* __restrict__ b1) {
    constexpr int CPS = KPAD / 64;
    constexpr int NCH = 3 * NKW * CPS;
    constexpr int ASTG = 128 * ROWB;
    constexpr int BBASE = 2 * ASTG;
    constexpr int BSTG = 128 * ROWB;
    extern __shared__ char smem[];
    const uint32_t sb = smem_u32(smem);
    const int tid = threadIdx.x, lane = tid & 31, wid = tid >> 5;
    const int m0 = blockIdx.y * 128, n0 = blockIdx.x * 128;
    const int wm = wid >> 1, wn = wid & 1;     // warp tile: 32m x 64n

    float acc[2][8][4];
#pragma unroll
    for (int i = 0; i < 2; i++)
#pragma unroll
        for (int j = 0; j < 8; j++)
#pragma unroll
            for (int k = 0; k < 4; k++) acc[i][j][k] = 0.f;

    auto load_stage = [&](int i, int st) {
        int seg = i / (NKW * CPS);
        int rem = i - seg * (NKW * CPS);
        int kw = rem / CPS;
        int c = rem - kw * CPS;
        int aoff = (seg == 1 ? KPAD : 0) + c * 64;
        int boff = kw * 2 * KPAD + (seg == 2 ? KPAD : 0) + c * 64;
        uint32_t sA = sb + st * ASTG;
        uint32_t sB = sb + BBASE + st * BSTG;
#pragma unroll
        for (int t = 0; t < 4; t++) {
            int idx = tid + t * 256;
            int row = idx >> 3, j = idx & 7;
            const __nv_bfloat16* src = A + (size_t)(m0 + row + kw) * lda + aoff + j * 8;
            CP_ASYNC16(sA + row * ROWB + j * 16, src);
        }
#pragma unroll
        for (int t = 0; t < 4; t++) {
            int idx = tid + t * 256;
            int row = idx >> 3, j = idx & 7;
            int n = n0 + row;
            int ok = (n < Ncols);
            const __nv_bfloat16* src = Bw + (size_t)(ok ? n : 0) * ldb + boff + j * 8;
            CP_ASYNC16Z(sB + row * ROWB + j * 16, src, ok ? 16 : 0);
        }
        CP_COMMIT();
    };

    const uint32_t aLane = (uint32_t)((wm * 32 + (lane & 15)) * ROWB + ((lane >> 4) * 8) * 2);
    const uint32_t bLane = (uint32_t)((wn * 64 + (lane & 7) + ((lane >> 4) * 8)) * ROWB +
                                      (((lane >> 3) & 1) * 8) * 2);

    load_stage(0, 0);
    for (int i = 0; i < NCH; i++) {
        int st = i & 1;
        if (i + 1 < NCH) { load_stage(i + 1, (i + 1) & 1); CP_WAIT(1); }
        else             { CP_WAIT(0); }
        __syncthreads();
        uint32_t aB = sb + st * ASTG + aLane;
        uint32_t bB = sb + BBASE + st * BSTG + bLane;
#pragma unroll
        for (int ks = 0; ks < 4; ks++) {
            uint32_t a0[4], a1[4], bf[4][4];
            LDSM4(a0, aB + ks * 32);
            LDSM4(a1, aB + 16 * ROWB + ks * 32);
#pragma unroll
            for (int j = 0; j < 4; j++)
                LDSM4(bf[j], bB + j * 16 * ROWB + ks * 32);
#pragma unroll
            for (int j = 0; j < 4; j++) {
                MMA16816(acc[0][2 * j],     a0, bf[j][0], bf[j][1]);
                MMA16816(acc[0][2 * j + 1], a0, bf[j][2], bf[j][3]);
                MMA16816(acc[1][2 * j],     a1, bf[j][0], bf[j][1]);
                MMA16816(acc[1][2 * j + 1], a1, bf[j][2], bf[j][3]);
            }
        }
        __syncthreads();
    }

    const int g = lane >> 2, tg = lane & 3;
#pragma unroll
    for (int mi = 0; mi < 2; mi++) {
        int mA = m0 + wm * 32 + mi * 16 + g;
#pragma unroll
        for (int nj = 0; nj < 8; nj++) {
            int n = n0 + wn * 64 + nj * 8 + tg * 2;
            float v0 = acc[mi][nj][0], v1 = acc[mi][nj][1];
            float v2 = acc[mi][nj][2], v3 = acc[mi][nj][3];
            if (EPI == 0 || EPI == 2) {
                if (n < Ncols) {
                    float bn = bias[n], bn1 = bias[n + 1];
                    v0 += bn; v1 += bn1; v2 += bn; v3 += bn1;
                    if (EPI == 2) {
                        v0 = fmaxf(v0, 0.f); v1 = fmaxf(v1, 0.f);
                        v2 = fmaxf(v2, 0.f); v3 = fmaxf(v3, 0.f);
                    }
                    *(float2*)&C[(size_t)mA * ldc + n] = make_float2(v0, v1);
                    *(float2*)&C[(size_t)(mA + 8) * ldc + n] = make_float2(v2, v3);
                }
            } else {
                uint32_t hi0 = 0, lo0 = 0, hi1 = 0, lo1 = 0;
                if (n < Ncols) {
                    float bn = bias[n], bn1 = bias[n + 1];
                    float dn = b1[n], dn1 = b1[n + 1];
                    float q0a = (float)cc0[mA], q1a = (float)cc1[mA];
                    float q0b = (float)cc0[mA + 8], q1b = (float)cc1[mA + 8];
                    v0 += q0a * bn + q1a * dn;   v1 += q0a * bn1 + q1a * dn1;
                    v2 += q0b * bn + q1b * dn;   v3 += q0b * bn1 + q1b * dn1;
                    __nv_bfloat16 h0, l0, h1, l1;
                    split2(v0, h0, l0); split2(v1, h1, l1);
                    hi0 = packbf(h0, h1); lo0 = packbf(l0, l1);
                    split2(v2, h0, l0); split2(v3, h1, l1);
                    hi1 = packbf(h0, h1); lo1 = packbf(l0, l1);
                }
                if (n < okpad) {
                    *(uint32_t*)&OS[(size_t)mA * (2 * okpad) + n] = hi0;
                    *(uint32_t*)&OS[(size_t)mA * (2 * okpad) + okpad + n] = lo0;
                    *(uint32_t*)&OS[(size_t)(mA + 8) * (2 * okpad) + n] = hi1;
                    *(uint32_t*)&OS[(size_t)(mA + 8) * (2 * okpad) + okpad + n] = lo1;
                }
            }
        }
    }
}

// ---------------- preprocessing kernels ----------------
__global__ void k_init_h(const float* __restrict__ x, float* __restrict__ h,
                         __nv_bfloat16* __restrict__ hs0, __nv_bfloat16* __restrict__ hs1) {
    int idx = blockIdx.x * blockDim.x + threadIdx.x;
    if (idx >= (NN + 2) * 256) return;
    int n = idx >> 8, c = idx & 255;
    __nv_bfloat16 z = __float2bfloat16(0.f);
    if (n >= NN) {
        hs0[(size_t)n * 512 + c] = z;      hs0[(size_t)n * 512 + 256 + c] = z;
        hs1[(size_t)n * 512 + c] = z;      hs1[(size_t)n * 512 + 256 + c] = z;
        return;
    }
    float v = (c < DD) ? x[(size_t)n * DD + c] : 0.f;
    if (c < HH) h[(size_t)n * HH + c] = v;
    __nv_bfloat16 hi, lo;
    split2(v, hi, lo);
    hs0[(size_t)n * 512 + c] = hi;
    hs0[(size_t)n * 512 + 256 + c] = lo;
}

__global__ void k_zero_cnt(int* __restrict__ c) {
    int idx = blockIdx.x * blockDim.x + threadIdx.x;
    if (idx < 2 * NN) c[idx] = 0;
}

__global__ void k_count(const int* __restrict__ eidx, const int* __restrict__ etyp,
                        int* __restrict__ cnt) {
    int e = blockIdx.x * blockDim.x + threadIdx.x;
    if (e >= EE) return;
    int d = eidx[EE + e] + (etyp[e] ? NN : 0);
    atomicAdd(&cnt[d], 1);
}

__global__ void k_scan1(const int* __restrict__ cnt, int* __restrict__ part) {
    __shared__ int sh[1024];
    int t = threadIdx.x;
    int v = cnt[blockIdx.x * 1024 + t];
    sh[t] = v;
    __syncthreads();
    for (int off = 512; off > 0; off >>= 1) {
        if (t < off) sh[t] += sh[t + off];
        __syncthreads();
    }
    if (t == 0) part[blockIdx.x] = sh[0];
}

__global__ void k_scan2(const int* __restrict__ part, int* __restrict__ pref,
                        int* __restrict__ rowptr) {
    __shared__ int sh[256];
    int t = threadIdx.x;
    int v = (t < 200) ? part[t] : 0;
    sh[t] = v;
    __syncthreads();
    for (int off = 1; off < 256; off <<= 1) {
        int u = (t >= off) ? sh[t - off] : 0;
        __syncthreads();
        sh[t] += u;
        __syncthreads();
    }
    if (t < 200) pref[t] = sh[t] - v;
    if (t == 0) rowptr[2 * NN] = EE;
}

__global__ void k_scan3(const int* __restrict__ cnt, const int* __restrict__ pref,
                        int* __restrict__ rowptr, int* __restrict__ rowfill) {
    __shared__ int sh[1024];
    int t = threadIdx.x;
    int i = blockIdx.x * 1024 + t;
    int v = cnt[i];
    sh[t] = v;
    __syncthreads();
    for (int off = 1; off < 1024; off <<= 1) {
        int u = (t >= off) ? sh[t - off] : 0;
        __syncthreads();
        sh[t] += u;
        __syncthreads();
    }
    int excl = sh[t] - v + pref[blockIdx.x];
    rowptr[i] = excl;
    rowfill[i] = excl;
}

__global__ void k_fill(const int* __restrict__ eidx, const int* __restrict__ etyp,
                       int* __restrict__ rowfill, int* __restrict__ col) {
    int e = blockIdx.x * blockDim.x + threadIdx.x;
    if (e >= EE) return;
    int d = eidx[EE + e] + (etyp[e] ? NN : 0);
    int p = atomicAdd(&rowfill[d], 1);
    col[p] = eidx[e];
}

__global__ void k_packw(const float* __restrict__ src, __nv_bfloat16* __restrict__ dst,
                        int O, int I, int KW, int KPAD) {
    int idx = blockIdx.x * blockDim.x + threadIdx.x;
    if (idx >= O * KW * KPAD) return;
    int o = idx / (KW * KPAD);
    int r = idx % (KW * KPAD);
    int kw = r / KPAD, c = r % KPAD;
    float v = (c < I) ? src[((size_t)o * I + c) * KW + kw] : 0.f;
    __nv_bfloat16 hi, lo;
    split2(v, hi, lo);
    size_t base = (size_t)o * (KW * 2 * KPAD) + (size_t)kw * 2 * KPAD;
    dst[base + c] = hi;
    dst[base + KPAD + c] = lo;
}

__global__ void k_wcat_split(const float* __restrict__ gW, __nv_bfloat16* __restrict__ dst) {
    int idx = blockIdx.x * blockDim.x + threadIdx.x;
    if (idx >= 200 * 448) return;
    int o = idx / 448, k = idx % 448;
    float v = 0.f;
    if (k < 200)      v = gW[(size_t)o * 200 + k];
    else if (k < 400) v = gW[(size_t)200 * 200 + (size_t)o * 200 + (k - 200)];
    __nv_bfloat16 hi, lo;
    split2(v, hi, lo);
    dst[(size_t)o * 896 + k] = hi;
    dst[(size_t)o * 896 + 448 + k] = lo;
}

// ---------------- gather: 64-thread group per (node, etype), float4 loads ----
__global__ void k_gather(const float* __restrict__ h, const int* __restrict__ rowptr,
                         const int* __restrict__ col, __nv_bfloat16* __restrict__ s) {
    int gid = (blockIdx.x * blockDim.x + threadIdx.x) >> 6;
    int t = threadIdx.x & 63;
    if (gid >= 2 * NN) return;
    int node = (gid < NN) ? gid : gid - NN;
    int ty   = (gid < NN) ? 0 : 1;
    bool act = (t < 50);
    float4 a = make_float4(0.f, 0.f, 0.f, 0.f);
    int beg = rowptr[gid], end = rowptr[gid + 1];
    for (int e = beg; e < end; e++) {
        const float4* hr = reinterpret_cast<const float4*>(h + (size_t)col[e] * HH);
        if (act) {
            float4 v = __ldg(hr + t);
            a.x += v.x; a.y += v.y; a.z += v.z; a.w += v.w;
        }
    }
    __nv_bfloat16* sr = s + (size_t)node * 896;
    if (act) {
        int c = ty * 200 + 4 * t;
        __nv_bfloat16 h0, l0, h1, l1;
        split2(a.x, h0, l0); split2(a.y, h1, l1);
        *(uint32_t*)&sr[c] = packbf(h0, h1);
        *(uint32_t*)&sr[448 + c] = packbf(l0, l1);
        split2(a.z, h0, l0); split2(a.w, h1, l1);
        *(uint32_t*)&sr[c + 2] = packbf(h0, h1);
        *(uint32_t*)&sr[448 + c + 2] = packbf(l0, l1);
    } else if (ty == 1 && t < 62) {
        int c = 400 + (t - 50) * 4;
        *(uint32_t*)&sr[c] = 0;       *(uint32_t*)&sr[c + 2] = 0;
        *(uint32_t*)&sr[448 + c] = 0; *(uint32_t*)&sr[448 + c + 2] = 0;
    }
}

__global__ void k_gru(const float* __restrict__ gi, const float* __restrict__ gh,
                      const float* __restrict__ h, float* __restrict__ hn,
                      __nv_bfloat16* __restrict__ hns) {
    int idx = blockIdx.x * blockDim.x + threadIdx.x;
    if (idx >= NN * 256) return;
    int n = idx >> 8, c = idx & 255;
    __nv_bfloat16* hp = hns + (size_t)n * 512;
    if (c >= HH) {
        __nv_bfloat16 z = __float2bfloat16(0.f);
        hp[c] = z; hp[256 + c] = z;
        return;
    }
    size_t base = (size_t)n * (3 * HH) + c;
    float ir = gi[base], iz = gi[base + HH], inn = gi[base + 2 * HH];
    float hr = gh[base], hz = gh[base + HH], hnn = gh[base + 2 * HH];
    float r = 1.f / (1.f + expf(-(ir + hr)));
    float z = 1.f / (1.f + expf(-(iz + hz)));
    float nv = tanhf(inn + r * hnn);
    float v = (1.f - z) * nv + z * h[(size_t)n * HH + c];
    hn[(size_t)n * HH + c] = v;
    __nv_bfloat16 hi, lo;
    split2(v, hi, lo);
    hp[c] = hi;
    hp[256 + c] = lo;
}

__global__ void k_catsplit(const float* __restrict__ x, const float* __restrict__ h,
                           __nv_bfloat16* __restrict__ dst) {
    int idx = blockIdx.x * blockDim.x + threadIdx.x;
    if (idx >= (NN + 2) * 320) return;
    int n = idx / 320, c = idx % 320;
    float v = 0.f;
    if (n < NN) v = (c < DD) ? x[(size_t)n * DD + c] : h[(size_t)n * HH + (c - DD)];
    __nv_bfloat16 hi, lo;
    split2(v, hi, lo);
    dst[(size_t)n * 640 + c] = hi;
    dst[(size_t)n * 640 + 320 + c] = lo;
}

__global__ void k_pool3s(const float* __restrict__ in, __nv_bfloat16* __restrict__ out,
                         int C, int KPAD) {
    int idx = blockIdx.x * blockDim.x + threadIdx.x;
    if (idx >= (MP + 2) * KPAD) return;
    int m = idx / KPAD, c = idx % KPAD;
    float v = 0.f;
    if (m < MP && c < C) {
        int b = m / 198, l = m % 198;
        size_t base = ((size_t)b * 400 + 2 * l) * C + c;
        v = fmaxf(fmaxf(in[base], in[base + C]), in[base + 2 * C]);
    }
    __nv_bfloat16 hi, lo;
    split2(v, hi, lo);
    out[(size_t)m * 2 * KPAD + c] = hi;
    out[(size_t)m * 2 * KPAD + KPAD + c] = lo;
}

__global__ void k_pool2s(const float* __restrict__ in, __nv_bfloat16* __restrict__ out,
                         int C, int KPAD) {
    int idx = blockIdx.x * blockDim.x + threadIdx.x;
    if (idx >= M2 * KPAD) return;
    int m = idx / KPAD, c = idx % KPAD;
    float v = 0.f;
    if (c < C) {
        int b = m / 99, l = m % 99;
        size_t base = ((size_t)b * 198 + 2 * l) * C + c;
        v = fmaxf(in[base], in[base + C]);
    }
    __nv_bfloat16 hi, lo;
    split2(v, hi, lo);
    out[(size_t)m * 2 * KPAD + c] = hi;
    out[(size_t)m * 2 * KPAD + KPAD + c] = lo;
}

__global__ void k_avg(const float* __restrict__ yp, const float* __restrict__ zp,
                      float* __restrict__ avg) {
    int idx = blockIdx.x * blockDim.x + threadIdx.x;
    if (idx >= BB * 256) return;
    int j = idx & 255;
    int b = idx >> 8;
    float s = 0.f;
    for (int l = 0; l < 99; l++) {
        size_t off = ((size_t)b * 99 + l) * 256 + j;
        s += yp[off] * zp[off];
    }
    avg[idx] = s * (1.f / 99.f);
}

// ---------------- tiny SIMT head GEMM ----------------
template<int EPI>
__global__ __launch_bounds__(256)
void gemm_tn(const float* __restrict__ A, const float* __restrict__ W,
             const float* __restrict__ bias, float* __restrict__ C,
             int M, int Nc, int K) {
    __shared__ float As[8][128];
    __shared__ float Ws[8][64];
    int tid = threadIdx.x;
    int m0 = blockIdx.y * 128;
    int n0 = blockIdx.x * 64;
    int msub = (tid >> 4) * 8;
    int nsub = (tid & 15) * 4;
    float acc[8][4];
#pragma unroll
    for (int i = 0; i < 8; i++)
#pragma unroll
        for (int j = 0; j < 4; j++) acc[i][j] = 0.f;
    int la_m = tid >> 1;
    int la_k = (tid & 1) * 4;
    int lw_n = tid >> 2;
    int lw_k = (tid & 3) * 2;
    for (int k0 = 0; k0 < K; k0 += 8) {
        float4 av = *(const float4*)(A + (size_t)(m0 + la_m) * K + k0 + la_k);
        As[la_k + 0][la_m] = av.x;
        As[la_k + 1][la_m] = av.y;
        As[la_k + 2][la_m] = av.z;
        As[la_k + 3][la_m] = av.w;
        float2 wv = make_float2(0.f, 0.f);
        if (n0 + lw_n < Nc)
            wv = *(const float2*)(W + (size_t)(n0 + lw_n) * K + k0 + lw_k);
        Ws[lw_k + 0][lw_n] = wv.x;
        Ws[lw_k + 1][lw_n] = wv.y;
        __syncthreads();
#pragma unroll
        for (int k = 0; k < 8; k++) {
            float4 a0 = *(const float4*)&As[k][msub];
            float4 a1 = *(const float4*)&As[k][msub + 4];
            float4 bv = *(const float4*)&Ws[k][nsub];
            float am[8] = {a0.x, a0.y, a0.z, a0.w, a1.x, a1.y, a1.z, a1.w};
            float bn[4] = {bv.x, bv.y, bv.z, bv.w};
#pragma unroll
            for (int i = 0; i < 8; i++)
#pragma unroll
                for (int j = 0; j < 4; j++) acc[i][j] += am[i] * bn[j];
        }
        __syncthreads();
    }
#pragma unroll
    for (int i = 0; i < 8; i++) {
        int m = m0 + msub + i;
#pragma unroll
        for (int j = 0; j < 4; j++) {
            int n = n0 + nsub + j;
            if (n < Nc) {
                float v = acc[i][j] + bias[n];
                if (EPI == 1) v = fmaxf(v, 0.f);
                C[(size_t)m * Nc + n] = v;
            }
        }
    }
}

__global__ void k_pack(const float* __restrict__ logits, const float* __restrict__ hf,
                       float* __restrict__ out, int out_size) {
    int i = blockIdx.x * blockDim.x + threadIdx.x;
    if (i >= out_size) return;
    out[i] = (i < BB * 2) ? logits[i] : hf[i - BB * 2];
}

// ---------------- launcher ----------------
extern "C" void kernel_launch(void* const* d_in, const int* in_sizes, int n_in,
                              void* d_out, int out_size) {
    const float* x    = (const float*)d_in[0];
    const int*   eidx = (const int*)d_in[1];
    const int*   etyp = (const int*)d_in[2];
    const float* ggnnW = (const float*)d_in[3];
    const float* ggnnB = (const float*)d_in[4];
    const float* Wih  = (const float*)d_in[5];
    const float* Whh  = (const float*)d_in[6];
    const float* bih  = (const float*)d_in[7];
    const float* bhh  = (const float*)d_in[8];
    const float* c1w  = (const float*)d_in[9];
    const float* c1b  = (const float*)d_in[10];
    const float* c2w  = (const float*)d_in[11];
    const float* c2b  = (const float*)d_in[12];
    const float* cc1w = (const float*)d_in[13];
    const float* cc1b = (const float*)d_in[14];
    const float* cc2w = (const float*)d_in[15];
    const float* cc2b = (const float*)d_in[16];
    const float* yw   = (const float*)d_in[17];
    const float* yb   = (const float*)d_in[18];
    const float* zw   = (const float*)d_in[19];
    const float* zb   = (const float*)d_in[20];
    const float* l1w  = (const float*)d_in[21];
    const float* l1b  = (const float*)d_in[22];
    const float* f1w  = (const float*)d_in[23];
    const float* f1b  = (const float*)d_in[24];
    const float* f2w  = (const float*)d_in[25];
    const float* f2b  = (const float*)d_in[26];
    const float* clsw = (const float*)d_in[27];
    const float* clsb = (const float*)d_in[28];
    float* out = (float*)d_out;

    void* p;
#define GET(name, sym, T) cudaGetSymbolAddress(&p, sym); T* name = (T*)p;
    GET(h0, g_h0, float) GET(h1, g_h1, float)
    GET(h0s, g_h0s, __nv_bfloat16) GET(h1s, g_h1s, __nv_bfloat16)
    GET(ss, g_ss, __nv_bfloat16) GET(as, g_as, __nv_bfloat16)
    GET(gi, g_gi, float) GET(gh, g_gh, float)
    GET(cnt, g_cnt, int) GET(rowptr, g_rowptr, int) GET(rowfill, g_rowfill, int)
    GET(colv, g_col, int) GET(part, g_part, int) GET(pref, g_pref, int)
    GET(wcs, g_wcat_s, __nv_bfloat16) GET(wis, g_wih_s, __nv_bfloat16) GET(whs, g_whh_s, __nv_bfloat16)
    GET(mys, g_myw_s, __nv_bfloat16) GET(mzs, g_mzw_s, __nv_bfloat16)
    GET(c1p, g_c1p, __nv_bfloat16) GET(c2p, g_c2p, __nv_bfloat16)
    GET(cc1p, g_cc1p, __nv_bfloat16) GET(cc2p, g_cc2p, __nv_bfloat16)
    GET(xcat, g_xcat, __nv_bfloat16)
    GET(y1g, g_y1g, float) GET(z1g, g_z1g, float)
    GET(y1s, g_y1s, __nv_bfloat16) GET(z1s, g_z1s, __nv_bfloat16)
    GET(y2g, g_y2g, float) GET(z2g, g_z2g, float)
    GET(y2ps, g_y2ps, __nv_bfloat16) GET(z2ps, g_z2ps, __nv_bfloat16)
    GET(yp, g_yp, float) GET(zp, g_zp, float) GET(avg, g_avg, float)
    GET(m1, g_m1, float) GET(m2v, g_m2, float) GET(hfv, g_hf, float) GET(logits, g_logits, float)
#undef GET

    const int SMEM = 4 * 128 * ROWB;   // 73728
    cudaFuncSetAttribute(gemm_mma<448, 1, 1>, cudaFuncAttributeMaxDynamicSharedMemorySize, SMEM);
    cudaFuncSetAttribute(gemm_mma<256, 1, 0>, cudaFuncAttributeMaxDynamicSharedMemorySize, SMEM);
    cudaFuncSetAttribute(gemm_mma<256, 3, 2>, cudaFuncAttributeMaxDynamicSharedMemorySize, SMEM);
    cudaFuncSetAttribute(gemm_mma<256, 1, 2>, cudaFuncAttributeMaxDynamicSharedMemorySize, SMEM);
    cudaFuncSetAttribute(gemm_mma<320, 3, 2>, cudaFuncAttributeMaxDynamicSharedMemorySize, SMEM);
    cudaFuncSetAttribute(gemm_mma<320, 1, 2>, cudaFuncAttributeMaxDynamicSharedMemorySize, SMEM);
    cudaFuncSetAttribute(gemm_mma<320, 1, 0>, cudaFuncAttributeMaxDynamicSharedMemorySize, SMEM);

    // ---- preprocessing ----
    k_init_h<<<((NN + 2) * 256 + 255) / 256, 256>>>(x, h0, h0s, h1s);
    k_zero_cnt<<<(2 * NN + 255) / 256, 256>>>(cnt);
    k_count<<<EE / 256, 256>>>(eidx, etyp, cnt);
    k_scan1<<<200, 1024>>>(cnt, part);
    k_scan2<<<1, 256>>>(part, pref, rowptr);
    k_scan3<<<200, 1024>>>(cnt, pref, rowptr, rowfill);
    k_fill<<<EE / 256, 256>>>(eidx, etyp, rowfill, colv);
    k_wcat_split<<<(200 * 448 + 255) / 256, 256>>>(ggnnW, wcs);
    k_packw<<<(600 * 256 + 255) / 256, 256>>>(Wih, wis, 600, 200, 1, 256);
    k_packw<<<(600 * 256 + 255) / 256, 256>>>(Whh, whs, 600, 200, 1, 256);
    k_packw<<<(256 * 256 + 255) / 256, 256>>>(yw, mys, 256, 200, 1, 256);
    k_packw<<<(256 * 320 + 255) / 256, 256>>>(zw, mzs, 256, 320, 1, 320);
    k_packw<<<(200 * 3 * 256 + 255) / 256, 256>>>(c1w, c1p, 200, 200, 3, 256);
    k_packw<<<(200 * 256 + 255) / 256, 256>>>(c2w, c2p, 200, 200, 1, 256);
    k_packw<<<(320 * 3 * 320 + 255) / 256, 256>>>(cc1w, cc1p, 320, 320, 3, 320);
    k_packw<<<(320 * 320 + 255) / 256, 256>>>(cc2w, cc2p, 320, 320, 1, 320);

    // ---- GGNN steps ----
    for (int s = 0; s < NSTEPS; s++) {
        float* hin  = (s & 1) ? h1 : h0;
        float* hout = (s & 1) ? h0 : h1;
        __nv_bfloat16* hins  = (s & 1) ? h1s : h0s;
        __nv_bfloat16* houts = (s & 1) ? h0s : h1s;
        k_gather<<<2 * NN / 4, 256>>>(hin, rowptr, colv, ss);
        gemm_mma<448, 1, 1><<<dim3(2, NN / 128), 256, SMEM>>>(
            ss, 896, wcs, 896, 200, nullptr, 0, ggnnB, as, 256, cnt, cnt + NN, ggnnB + 200);
        gemm_mma<256, 1, 0><<<dim3(5, NN / 128), 256, SMEM>>>(
            as, 512, wis, 512, 600, gi, 600, bih, nullptr, 0, nullptr, nullptr, nullptr);
        gemm_mma<256, 1, 0><<<dim3(5, NN / 128), 256, SMEM>>>(
            hins, 512, whs, 512, 600, gh, 600, bhh, nullptr, 0, nullptr, nullptr, nullptr);
        k_gru<<<(NN * 256 + 255) / 256, 256>>>(gi, gh, hin, hout, houts);
    }
    // final h in h0 / h0s

    // ---- readout (all HMMA) ----
    k_catsplit<<<((NN + 2) * 320 + 255) / 256, 256>>>(x, h0, xcat);

    gemm_mma<256, 3, 2><<<dim3(2, NN / 128), 256, SMEM>>>(
        h0s, 512, c1p, 1536, 200, y1g, 200, c1b, nullptr, 0, nullptr, nullptr, nullptr);
    k_pool3s<<<((MP + 2) * 256 + 255) / 256, 256>>>(y1g, y1s, 200, 256);
    gemm_mma<256, 1, 2><<<dim3(2, MP / 128), 256, SMEM>>>(
        y1s, 512, c2p, 512, 200, y2g, 200, c2b, nullptr, 0, nullptr, nullptr, nullptr);
    k_pool2s<<<(M2 * 256 + 255) / 256, 256>>>(y2g, y2ps, 200, 256);

    gemm_mma<320, 3, 2><<<dim3(3, NN / 128), 256, SMEM>>>(
        xcat, 640, cc1p, 1920, 320, z1g, 320, cc1b, nullptr, 0, nullptr, nullptr, nullptr);
    k_pool3s<<<((MP + 2) * 320 + 255) / 256, 256>>>(z1g, z1s, 320, 320);
    gemm_mma<320, 1, 2><<<dim3(3, MP / 128), 256, SMEM>>>(
        z1s, 640, cc2p, 640, 320, z2g, 320, cc2b, nullptr, 0, nullptr, nullptr, nullptr);
    k_pool2s<<<(M2 * 320 + 255) / 256, 256>>>(z2g, z2ps, 320, 320);

    gemm_mma<256, 1, 0><<<dim3(2, M2 / 128), 256, SMEM>>>(
        y2ps, 512, mys, 512, 256, yp, 256, yb, nullptr, 0, nullptr, nullptr, nullptr);
    gemm_mma<320, 1, 0><<<dim3(2, M2 / 128), 256, SMEM>>>(
        z2ps, 640, mzs, 640, 256, zp, 256, zb, nullptr, 0, nullptr, nullptr, nullptr);
    k_avg<<<(BB * 256 + 255) / 256, 256>>>(yp, zp, avg);

    gemm_tn<1><<<dim3(2, 2), 256>>>(avg, l1w, l1b, m1, BB, 128, 256);
    gemm_tn<1><<<dim3(1, 2), 256>>>(m1, f1w, f1b, m2v, BB, 64, 128);
    gemm_tn<1><<<dim3(2, 2), 256>>>(m2v, f2w, f2b, hfv, BB, 128, 64);
    gemm_tn<0><<<dim3(1, 2), 256>>>(hfv, clsw, clsb, logits, BB, 2, 128);

    k_pack<<<(out_size + 255) / 256, 256>>>(logits, hfv, out, out_size);
    (void)n_in; (void)in_sizes;
}